// round 3
// baseline (speedup 1.0000x reference)
#include <cuda_runtime.h>

// ---------------- scratch (allocation-free rule: __device__ globals) ----------
// layouts: g_q/g_k/g_v : [B, H, N, 64]   g_ao : [B, N, 768]
__device__ float g_q[2 * 12 * 2048 * 64];
__device__ float g_k[2 * 12 * 2048 * 64];
__device__ float g_v[2 * 12 * 2048 * 64];
__device__ float g_ao[2 * 2048 * 768];
__device__ float g_mneg[2 * 2048];   // 0.0 (keep) or -1e30 (masked key)

// =============================================================================
// Kernel 0: mask dtype sniffer + conversion. 1 block, 256 threads.
// The harness widens the JAX bool mask to an unknown dtype. Detect it from the
// first 4096 bytes (in-bounds for uint8/int32/float32 interpretations):
//   all words in {0,1}           -> int32
//   all words in {0,0x3F800000}  -> float32
//   otherwise                    -> uint8 (packed random 0/1 bytes)
// =============================================================================
__global__ void mask_prep(const unsigned int* __restrict__ mw) {
    const int tid = threadIdx.x;
    int ok_int = 1, ok_flt = 1;
    for (int i = tid; i < 1024; i += 256) {
        unsigned int v = mw[i];
        if (v != 0u && v != 1u) ok_int = 0;
        if (v != 0u && v != 0x3F800000u) ok_flt = 0;
    }
    ok_int = __syncthreads_and(ok_int);
    ok_flt = __syncthreads_and(ok_flt);

    if (ok_int) {
        const int* m = (const int*)mw;
        for (int i = tid; i < 4096; i += 256)
            g_mneg[i] = m[i] ? -1e30f : 0.0f;
    } else if (ok_flt) {
        const float* m = (const float*)mw;
        for (int i = tid; i < 4096; i += 256)
            g_mneg[i] = (m[i] != 0.0f) ? -1e30f : 0.0f;
    } else {
        const unsigned char* m = (const unsigned char*)mw;
        for (int i = tid; i < 4096; i += 256)
            g_mneg[i] = m[i] ? -1e30f : 0.0f;
    }
}

// =============================================================================
// Kernel 1: QKV GEMM.  C[4096, 2304] = X[4096,768] @ W[768,2304] + b
// 128x128 block tile, BK=8, 256 threads, 8x8 micro-tile.
// Epilogue scatters into g_q/g_k/g_v with [B,H,N,64] layout.
// =============================================================================
__global__ __launch_bounds__(256) void qkv_gemm(const float* __restrict__ X,
                                                const float* __restrict__ W,
                                                const float* __restrict__ Bv) {
    __shared__ float As[8][128];   // [k][m] (A transposed)
    __shared__ float Bs[8][128];   // [k][n]
    const int tid = threadIdx.x;
    const int bM = blockIdx.y * 128, bN = blockIdx.x * 128;
    const int aRow = tid >> 1, aCol = (tid & 1) * 4;
    const int bRow = tid >> 5, bCol = (tid & 31) * 4;
    const int ty = tid >> 4, tx = tid & 15;

    float acc[8][8];
#pragma unroll
    for (int i = 0; i < 8; i++)
#pragma unroll
        for (int j = 0; j < 8; j++) acc[i][j] = 0.f;

    const float* Aptr = X + (bM + aRow) * 768 + aCol;
    const float* Bptr = W + bRow * 2304 + bN + bCol;

    for (int k0 = 0; k0 < 768; k0 += 8) {
        float4 a = *(const float4*)(Aptr + k0);
        float4 bv = *(const float4*)(Bptr + (size_t)k0 * 2304);
        As[aCol + 0][aRow] = a.x; As[aCol + 1][aRow] = a.y;
        As[aCol + 2][aRow] = a.z; As[aCol + 3][aRow] = a.w;
        *(float4*)&Bs[bRow][bCol] = bv;
        __syncthreads();
#pragma unroll
        for (int kk = 0; kk < 8; kk++) {
            float ar[8], br[8];
            *(float4*)&ar[0] = *(const float4*)&As[kk][ty * 8];
            *(float4*)&ar[4] = *(const float4*)&As[kk][ty * 8 + 4];
            *(float4*)&br[0] = *(const float4*)&Bs[kk][tx * 8];
            *(float4*)&br[4] = *(const float4*)&Bs[kk][tx * 8 + 4];
#pragma unroll
            for (int i = 0; i < 8; i++)
#pragma unroll
                for (int j = 0; j < 8; j++) acc[i][j] += ar[i] * br[j];
        }
        __syncthreads();
    }

    // epilogue: col -> (which q/k/v, head, hd).  A thread's 8 cols never straddle
    // a 64-boundary (col0 is 8-aligned) nor a 768-boundary (128 | 768).
    const int col0 = bN + tx * 8;
    const int which = col0 / 768;
    const int rem = col0 % 768;
    const int hh = rem / 64, hd0 = rem % 64;
    float* dst = (which == 0) ? g_q : (which == 1 ? g_k : g_v);
    float bb[8];
#pragma unroll
    for (int j = 0; j < 8; j++) bb[j] = Bv[col0 + j];
#pragma unroll
    for (int i = 0; i < 8; i++) {
        int row = bM + ty * 8 + i;
        int bidx = row >> 11, n = row & 2047;
        float* p = dst + ((((size_t)bidx * 12 + hh) * 2048 + n) * 64 + hd0);
        float4 v0 = make_float4(acc[i][0] + bb[0], acc[i][1] + bb[1],
                                acc[i][2] + bb[2], acc[i][3] + bb[3]);
        float4 v1 = make_float4(acc[i][4] + bb[4], acc[i][5] + bb[5],
                                acc[i][6] + bb[6], acc[i][7] + bb[7]);
        *(float4*)p = v0;
        *(float4*)(p + 4) = v1;
    }
}

// =============================================================================
// Kernel 2: flash attention per (qtile=64, h, b). 256 threads = 8 warps.
// Warp w owns query rows w*8..w*8+7; lane owns key cols {lane, lane+32}.
// =============================================================================
__global__ __launch_bounds__(256) void attn_kernel(const int* __restrict__ dist,
                                                   const float* __restrict__ bias_table) {
    extern __shared__ float sm[];
    float* Qs  = sm;                 // [64][64]
    float* Kst = Qs + 64 * 64;       // [d][j] with ld 65 (pad kills STS conflicts)
    float* Vs  = Kst + 64 * 65;      // [j][d]
    float* Ps  = Vs + 64 * 64;       // [i][j]
    float* btc = Ps + 64 * 64;       // [32] bias_table column for head h
    float* mng = btc + 32;           // [64] -1e30 if masked else 0

    const int qt = blockIdx.x, h = blockIdx.y, b = blockIdx.z;
    const int tid = threadIdx.x, w = tid >> 5, lane = tid & 31;

    const float* qbase = g_q + (((size_t)(b * 12 + h)) * 2048 + qt * 64) * 64;
    for (int v = tid; v < 1024; v += 256) {
        int i = v >> 4, d4 = (v & 15) << 2;
        *(float4*)&Qs[i * 64 + d4] = *(const float4*)&qbase[i * 64 + d4];
    }
    if (tid < 32) btc[tid] = bias_table[tid * 12 + h];

    float m[8], l[8], acc[8][2];
#pragma unroll
    for (int r = 0; r < 8; r++) {
        m[r] = -1e30f; l[r] = 0.f; acc[r][0] = 0.f; acc[r][1] = 0.f;
    }
    const float scale = 0.125f;  // 64^-0.5
    const int i0 = qt * 64 + w * 8;
    const int* drow = dist + ((size_t)b * 2048 + i0) * 2048;

    for (int kt = 0; kt < 32; kt++) {
        __syncthreads();  // protects Kst/Vs/Ps reuse + first-iter Qs/btc visibility
        const float* kb = g_k + (((size_t)(b * 12 + h)) * 2048 + kt * 64) * 64;
        const float* vb = g_v + (((size_t)(b * 12 + h)) * 2048 + kt * 64) * 64;
        for (int v = tid; v < 1024; v += 256) {
            int j = v >> 4, d4 = (v & 15) << 2;
            float4 t = *(const float4*)&kb[j * 64 + d4];
            Kst[(d4 + 0) * 65 + j] = t.x;
            Kst[(d4 + 1) * 65 + j] = t.y;
            Kst[(d4 + 2) * 65 + j] = t.z;
            Kst[(d4 + 3) * 65 + j] = t.w;
            *(float4*)&Vs[j * 64 + d4] = *(const float4*)&vb[j * 64 + d4];
        }
        if (tid < 64) mng[tid] = g_mneg[b * 2048 + kt * 64 + tid];
        __syncthreads();

        // ---- scores: s[r][{0,1}] = Q[i0+r] . K[{lane,lane+32}]
        float s[8][2];
#pragma unroll
        for (int r = 0; r < 8; r++) { s[r][0] = 0.f; s[r][1] = 0.f; }
#pragma unroll
        for (int d4 = 0; d4 < 64; d4 += 4) {
            float ka[4], kb2[4];
#pragma unroll
            for (int t = 0; t < 4; t++) {
                ka[t]  = Kst[(d4 + t) * 65 + lane];        // conflict-free (consecutive)
                kb2[t] = Kst[(d4 + t) * 65 + lane + 32];
            }
#pragma unroll
            for (int r = 0; r < 8; r++) {
                float4 q = *(const float4*)&Qs[(w * 8 + r) * 64 + d4];  // broadcast
                s[r][0] += q.x * ka[0] + q.y * ka[1] + q.z * ka[2] + q.w * ka[3];
                s[r][1] += q.x * kb2[0] + q.y * kb2[1] + q.z * kb2[2] + q.w * kb2[3];
            }
        }

        // ---- bias + mask + online softmax
        const int jg = kt * 64 + lane;
#pragma unroll
        for (int r = 0; r < 8; r++) {
            int dd0 = drow[r * 2048 + jg];
            int dd1 = drow[r * 2048 + jg + 32];
            dd0 = min(max(dd0, 0), 31);
            dd1 = min(max(dd1, 0), 31);
            float s0 = s[r][0] * scale + btc[dd0] + mng[lane];
            float s1 = s[r][1] * scale + btc[dd1] + mng[lane + 32];
            float mx = fmaxf(s0, s1);
#pragma unroll
            for (int o = 16; o > 0; o >>= 1)
                mx = fmaxf(mx, __shfl_xor_sync(0xffffffffu, mx, o));
            float mn = fmaxf(m[r], mx);
            float corr = __expf(m[r] - mn);
            m[r] = mn;
            float p0 = __expf(s0 - mn);
            float p1 = __expf(s1 - mn);
            l[r] = l[r] * corr + p0 + p1;     // per-lane partial; reduced at end
            acc[r][0] *= corr;
            acc[r][1] *= corr;
            Ps[(w * 8 + r) * 64 + lane] = p0;
            Ps[(w * 8 + r) * 64 + lane + 32] = p1;
        }
        __syncwarp();  // Ps rows are warp-private: warp-sync suffices

        // ---- O += P @ V   (P broadcast via float4, V conflict-free)
#pragma unroll
        for (int j4 = 0; j4 < 64; j4 += 4) {
            float v0[4], v1[4];
#pragma unroll
            for (int t = 0; t < 4; t++) {
                v0[t] = Vs[(j4 + t) * 64 + lane];
                v1[t] = Vs[(j4 + t) * 64 + lane + 32];
            }
#pragma unroll
            for (int r = 0; r < 8; r++) {
                const float4 p = *(const float4*)&Ps[(w * 8 + r) * 64 + j4];
                acc[r][0] += p.x * v0[0] + p.y * v0[1] + p.z * v0[2] + p.w * v0[3];
                acc[r][1] += p.x * v1[0] + p.y * v1[1] + p.z * v1[2] + p.w * v1[3];
            }
        }
    }

    // ---- epilogue: reduce l across lanes, normalize, write [B,N,768]
#pragma unroll
    for (int r = 0; r < 8; r++) {
        float ls = l[r];
#pragma unroll
        for (int o = 16; o > 0; o >>= 1)
            ls += __shfl_xor_sync(0xffffffffu, ls, o);
        float inv = 1.0f / ls;
        size_t base = ((size_t)b * 2048 + (i0 + r)) * 768 + h * 64;
        g_ao[base + lane]      = acc[r][0] * inv;
        g_ao[base + lane + 32] = acc[r][1] * inv;
    }
}

// =============================================================================
// Kernel 3: out projection.  out[4096,768] = g_ao[4096,768] @ W[768,768] + b
// =============================================================================
__global__ __launch_bounds__(256) void proj_gemm(const float* __restrict__ W,
                                                 const float* __restrict__ Bv,
                                                 float* __restrict__ out) {
    __shared__ float As[8][128];
    __shared__ float Bs[8][128];
    const int tid = threadIdx.x;
    const int bM = blockIdx.y * 128, bN = blockIdx.x * 128;
    const int aRow = tid >> 1, aCol = (tid & 1) * 4;
    const int bRow = tid >> 5, bCol = (tid & 31) * 4;
    const int ty = tid >> 4, tx = tid & 15;

    float acc[8][8];
#pragma unroll
    for (int i = 0; i < 8; i++)
#pragma unroll
        for (int j = 0; j < 8; j++) acc[i][j] = 0.f;

    const float* Aptr = g_ao + (size_t)(bM + aRow) * 768 + aCol;
    const float* Bptr = W + bRow * 768 + bN + bCol;

    for (int k0 = 0; k0 < 768; k0 += 8) {
        float4 a = *(const float4*)(Aptr + k0);
        float4 bv = *(const float4*)(Bptr + (size_t)k0 * 768);
        As[aCol + 0][aRow] = a.x; As[aCol + 1][aRow] = a.y;
        As[aCol + 2][aRow] = a.z; As[aCol + 3][aRow] = a.w;
        *(float4*)&Bs[bRow][bCol] = bv;
        __syncthreads();
#pragma unroll
        for (int kk = 0; kk < 8; kk++) {
            float ar[8], br[8];
            *(float4*)&ar[0] = *(const float4*)&As[kk][ty * 8];
            *(float4*)&ar[4] = *(const float4*)&As[kk][ty * 8 + 4];
            *(float4*)&br[0] = *(const float4*)&Bs[kk][tx * 8];
            *(float4*)&br[4] = *(const float4*)&Bs[kk][tx * 8 + 4];
#pragma unroll
            for (int i = 0; i < 8; i++)
#pragma unroll
                for (int j = 0; j < 8; j++) acc[i][j] += ar[i] * br[j];
        }
        __syncthreads();
    }

    const int col0 = bN + tx * 8;
    float bb[8];
#pragma unroll
    for (int j = 0; j < 8; j++) bb[j] = Bv[col0 + j];
#pragma unroll
    for (int i = 0; i < 8; i++) {
        int row = bM + ty * 8 + i;
        float* p = out + (size_t)row * 768 + col0;
        float4 v0 = make_float4(acc[i][0] + bb[0], acc[i][1] + bb[1],
                                acc[i][2] + bb[2], acc[i][3] + bb[3]);
        float4 v1 = make_float4(acc[i][4] + bb[4], acc[i][5] + bb[5],
                                acc[i][6] + bb[6], acc[i][7] + bb[7]);
        *(float4*)p = v0;
        *(float4*)(p + 4) = v1;
    }
}

// =============================================================================
extern "C" void kernel_launch(void* const* d_in, const int* in_sizes, int n_in,
                              void* d_out, int out_size) {
    const float* x          = (const float*)d_in[0];
    const int* dist         = (const int*)d_in[1];
    const unsigned int* mk  = (const unsigned int*)d_in[2];
    const float* qkv_w      = (const float*)d_in[3];
    const float* qkv_b      = (const float*)d_in[4];
    const float* out_w      = (const float*)d_in[5];
    const float* out_b      = (const float*)d_in[6];
    const float* bt         = (const float*)d_in[7];
    float* out              = (float*)d_out;

    mask_prep<<<1, 256>>>(mk);

    dim3 g1(18, 32);
    qkv_gemm<<<g1, 256>>>(x, qkv_w, qkv_b);

    const int smem = (64 * 64 + 64 * 65 + 64 * 64 + 64 * 64 + 32 + 64) * 4;  // ~66 KB
    cudaFuncSetAttribute(attn_kernel, cudaFuncAttributeMaxDynamicSharedMemorySize, smem);
    dim3 g2(32, 12, 2);
    attn_kernel<<<g2, 256, smem>>>(dist, bt);

    dim3 g3(6, 32);
    proj_gemm<<<g3, 256>>>(out_w, out_b, out);
}

// round 6
// speedup vs baseline: 1.4346x; 1.4346x over previous
#include <cuda_runtime.h>
#include <cstdint>

// ---------------- scratch (allocation-free rule: __device__ globals) ----------
// g_q/g_k/g_v : [B,H,N,64]  (tf32-rounded; q pre-scaled by 0.125)   g_ao : [B,N,768]
__device__ float g_q[2 * 12 * 2048 * 64];
__device__ float g_k[2 * 12 * 2048 * 64];
__device__ float g_v[2 * 12 * 2048 * 64];
__device__ float g_ao[2 * 2048 * 768];
__device__ float g_mneg[2 * 2048];                  // 0 or -1e30 per key
__device__ unsigned char g_dist8[2 * 2048 * 2048];  // clipped dist, 1 byte

__device__ __forceinline__ float to_tf32(float x) {
    float r;
    asm("cvt.rna.tf32.f32 %0, %1;" : "=f"(r) : "f"(x));
    return r;
}
// mma.sync m16n8k8 tf32 (sm_80+ path; compiles for plain sm_103 targets)
__device__ __forceinline__ void mma8(float* c, const uint32_t* a, const uint32_t* b) {
    asm("mma.sync.aligned.m16n8k8.row.col.f32.tf32.tf32.f32 "
        "{%0,%1,%2,%3},{%4,%5,%6,%7},{%8,%9},{%0,%1,%2,%3};"
        : "+f"(c[0]), "+f"(c[1]), "+f"(c[2]), "+f"(c[3])
        : "r"(a[0]), "r"(a[1]), "r"(a[2]), "r"(a[3]), "r"(b[0]), "r"(b[1]));
}

// =============================================================================
// Kernel 0a: mask dtype sniffer + conversion (validated R3)
// =============================================================================
__global__ void mask_prep(const unsigned int* __restrict__ mw) {
    const int tid = threadIdx.x;
    int ok_int = 1, ok_flt = 1;
    for (int i = tid; i < 1024; i += 256) {
        unsigned int v = mw[i];
        if (v != 0u && v != 1u) ok_int = 0;
        if (v != 0u && v != 0x3F800000u) ok_flt = 0;
    }
    ok_int = __syncthreads_and(ok_int);
    ok_flt = __syncthreads_and(ok_flt);
    if (ok_int) {
        const int* m = (const int*)mw;
        for (int i = tid; i < 4096; i += 256) g_mneg[i] = m[i] ? -1e30f : 0.0f;
    } else if (ok_flt) {
        const float* m = (const float*)mw;
        for (int i = tid; i < 4096; i += 256) g_mneg[i] = (m[i] != 0.0f) ? -1e30f : 0.0f;
    } else {
        const unsigned char* m = (const unsigned char*)mw;
        for (int i = tid; i < 4096; i += 256) g_mneg[i] = m[i] ? -1e30f : 0.0f;
    }
}

// =============================================================================
// Kernel 0b: pack dist int32 -> clipped uint8
// =============================================================================
__global__ void dist_pack(const int* __restrict__ dist) {
    size_t i = ((size_t)blockIdx.x * 256 + threadIdx.x) * 8;
    int4 a = *(const int4*)(dist + i);
    int4 b = *(const int4*)(dist + i + 4);
    unsigned c0 = (unsigned)min(max(a.x, 0), 31) | ((unsigned)min(max(a.y, 0), 31) << 8) |
                  ((unsigned)min(max(a.z, 0), 31) << 16) | ((unsigned)min(max(a.w, 0), 31) << 24);
    unsigned c1 = (unsigned)min(max(b.x, 0), 31) | ((unsigned)min(max(b.y, 0), 31) << 8) |
                  ((unsigned)min(max(b.z, 0), 31) << 16) | ((unsigned)min(max(b.w, 0), 31) << 24);
    *(uint2*)(g_dist8 + i) = make_uint2(c0, c1);
}

// =============================================================================
// Kernel 1: QKV GEMM (validated R3) — epilogue tf32-rounds Q/K/V, Q*0.125
// =============================================================================
__global__ __launch_bounds__(256) void qkv_gemm(const float* __restrict__ X,
                                                const float* __restrict__ W,
                                                const float* __restrict__ Bv) {
    __shared__ float As[8][128];
    __shared__ float Bs[8][128];
    const int tid = threadIdx.x;
    const int bM = blockIdx.y * 128, bN = blockIdx.x * 128;
    const int aRow = tid >> 1, aCol = (tid & 1) * 4;
    const int bRow = tid >> 5, bCol = (tid & 31) * 4;
    const int ty = tid >> 4, tx = tid & 15;

    float acc[8][8];
#pragma unroll
    for (int i = 0; i < 8; i++)
#pragma unroll
        for (int j = 0; j < 8; j++) acc[i][j] = 0.f;

    const float* Aptr = X + (bM + aRow) * 768 + aCol;
    const float* Bptr = W + bRow * 2304 + bN + bCol;

    for (int k0 = 0; k0 < 768; k0 += 8) {
        float4 a = *(const float4*)(Aptr + k0);
        float4 bv = *(const float4*)(Bptr + (size_t)k0 * 2304);
        As[aCol + 0][aRow] = a.x; As[aCol + 1][aRow] = a.y;
        As[aCol + 2][aRow] = a.z; As[aCol + 3][aRow] = a.w;
        *(float4*)&Bs[bRow][bCol] = bv;
        __syncthreads();
#pragma unroll
        for (int kk = 0; kk < 8; kk++) {
            float ar[8], br[8];
            *(float4*)&ar[0] = *(const float4*)&As[kk][ty * 8];
            *(float4*)&ar[4] = *(const float4*)&As[kk][ty * 8 + 4];
            *(float4*)&br[0] = *(const float4*)&Bs[kk][tx * 8];
            *(float4*)&br[4] = *(const float4*)&Bs[kk][tx * 8 + 4];
#pragma unroll
            for (int i = 0; i < 8; i++)
#pragma unroll
                for (int j = 0; j < 8; j++) acc[i][j] += ar[i] * br[j];
        }
        __syncthreads();
    }

    const int col0 = bN + tx * 8;
    const int which = col0 / 768;
    const int rem = col0 % 768;
    const int hh = rem / 64, hd0 = rem % 64;
    float* dst = (which == 0) ? g_q : (which == 1 ? g_k : g_v);
    const float qscale = (which == 0) ? 0.125f : 1.0f;
    float bb[8];
#pragma unroll
    for (int j = 0; j < 8; j++) bb[j] = Bv[col0 + j];
#pragma unroll
    for (int i = 0; i < 8; i++) {
        int row = bM + ty * 8 + i;
        int bidx = row >> 11, n = row & 2047;
        float* p = dst + ((((size_t)bidx * 12 + hh) * 2048 + n) * 64 + hd0);
        float vv[8];
#pragma unroll
        for (int j = 0; j < 8; j++) vv[j] = to_tf32((acc[i][j] + bb[j]) * qscale);
        *(float4*)p = make_float4(vv[0], vv[1], vv[2], vv[3]);
        *(float4*)(p + 4) = make_float4(vv[4], vv[5], vv[6], vv[7]);
    }
}

// =============================================================================
// Kernel 2: tf32 mma.sync flash attention.
// CTA = 64 queries (4 warps x 16 rows) x full key sweep (32 tiles of 64 keys).
// Q fragments register-resident; K/V/dist staged in smem; P via smem (layout fix).
// =============================================================================
static constexpr int KS_OFF = 0;             // [64][68] f32 = 17408 B
static constexpr int VS_OFF = 17408;         // [64][68] f32
static constexpr int PS_OFF = 34816;         // [64][68] f32
static constexpr int DS_OFF = 52224;         // [64][64] u8 = 4096 B
static constexpr int BT_OFF = 56320;         // 32 f32
static constexpr int MNG_OFF = 56448;        // 64 f32
static constexpr int ATTN_SMEM = 56704;

__global__ __launch_bounds__(128) void attn_mma(const float* __restrict__ bias_table) {
    extern __shared__ char smem[];
    float* Ks = (float*)(smem + KS_OFF);
    float* Vs = (float*)(smem + VS_OFF);
    float* Ps = (float*)(smem + PS_OFF);
    unsigned char* Ds = (unsigned char*)(smem + DS_OFF);
    float* btc = (float*)(smem + BT_OFF);
    float* mng = (float*)(smem + MNG_OFF);

    const int tid = threadIdx.x, w = tid >> 5, l = tid & 31;
    const int gid = l >> 2, tig = l & 3;   // group-in-warp (row), thread-in-group (col)
    const int qt = blockIdx.x, h = blockIdx.y, b = blockIdx.z;
    const size_t bh = (size_t)b * 12 + h;

    // ---- Q fragments (register-resident across whole key sweep)
    uint32_t Qa[8][4];
    {
        const float* qb = g_q + ((bh * 2048) + qt * 64 + w * 16) * 64;
#pragma unroll
        for (int s = 0; s < 8; s++) {
            Qa[s][0] = __float_as_uint(qb[gid * 64 + s * 8 + tig]);
            Qa[s][1] = __float_as_uint(qb[(gid + 8) * 64 + s * 8 + tig]);
            Qa[s][2] = __float_as_uint(qb[gid * 64 + s * 8 + tig + 4]);
            Qa[s][3] = __float_as_uint(qb[(gid + 8) * 64 + s * 8 + tig + 4]);
        }
    }
    if (tid < 32) btc[tid] = bias_table[tid * 12 + h];

    float O[8][4];
#pragma unroll
    for (int n = 0; n < 8; n++)
#pragma unroll
        for (int j = 0; j < 4; j++) O[n][j] = 0.f;
    float lsum0 = 0.f, lsum1 = 0.f;

    const int row = tid >> 1, half = tid & 1;  // smem-fill mapping

    for (int kt = 0; kt < 32; kt++) {
        __syncthreads();  // all warps done with previous K/V/Ds (+ btc visibility on iter 0)
        // ---- stage K, V (64x64 f32 each), dist tile (64x64 u8), mask
        {
            const float* kr = g_k + (bh * 2048 + kt * 64 + row) * 64 + half * 32;
            const float* vr = g_v + (bh * 2048 + kt * 64 + row) * 64 + half * 32;
            float* kd = Ks + row * 68 + half * 32;
            float* vd = Vs + row * 68 + half * 32;
#pragma unroll
            for (int c = 0; c < 8; c++) {
                *(float4*)(kd + c * 4) = *(const float4*)(kr + c * 4);
                *(float4*)(vd + c * 4) = *(const float4*)(vr + c * 4);
            }
            const unsigned char* dr =
                g_dist8 + ((size_t)(b * 2048 + qt * 64 + row)) * 2048 + kt * 64 + half * 32;
            *(uint4*)(Ds + row * 64 + half * 32) = *(const uint4*)dr;
            *(uint4*)(Ds + row * 64 + half * 32 + 16) = *(const uint4*)(dr + 16);
        }
        if (tid < 64) mng[tid] = g_mneg[b * 2048 + kt * 64 + tid];
        __syncthreads();

        // ---- S = Q @ K^T  (per warp: 16 rows x 64 keys)
        float S[8][4];
#pragma unroll
        for (int n = 0; n < 8; n++)
#pragma unroll
            for (int j = 0; j < 4; j++) S[n][j] = 0.f;
#pragma unroll
        for (int s = 0; s < 8; s++) {
            uint32_t Bf[8][2];
#pragma unroll
            for (int n = 0; n < 8; n++) {
                Bf[n][0] = __float_as_uint(Ks[(n * 8 + gid) * 68 + s * 8 + tig]);
                Bf[n][1] = __float_as_uint(Ks[(n * 8 + gid) * 68 + s * 8 + tig + 4]);
            }
#pragma unroll
            for (int n = 0; n < 8; n++) mma8(S[n], Qa[s], Bf[n]);
        }

        // ---- softmax (no running max needed: |args| bounded ~13) + P -> Ps
        // FIX(R5): dist rows must include this warp's row offset w*16.
        const unsigned char* d0p = Ds + (w * 16 + gid) * 64;
        const unsigned char* d1p = Ds + (w * 16 + gid + 8) * 64;
        const int prow = w * 16 + gid;
#pragma unroll
        for (int n = 0; n < 8; n++) {
            const int c0 = n * 8 + tig * 2;
            const float mg0 = mng[c0], mg1 = mng[c0 + 1];
            float p00 = to_tf32(__expf(S[n][0] + btc[d0p[c0]] + mg0));
            float p01 = to_tf32(__expf(S[n][1] + btc[d0p[c0 + 1]] + mg1));
            float p10 = to_tf32(__expf(S[n][2] + btc[d1p[c0]] + mg0));
            float p11 = to_tf32(__expf(S[n][3] + btc[d1p[c0 + 1]] + mg1));
            lsum0 += p00 + p01;
            lsum1 += p10 + p11;
            *(float2*)&Ps[prow * 68 + c0] = make_float2(p00, p01);
            *(float2*)&Ps[(prow + 8) * 68 + c0] = make_float2(p10, p11);
        }
        __syncwarp();  // Ps section is warp-private

        // ---- O += P @ V   (k dim = 64 keys, 8 steps)
#pragma unroll
        for (int kk = 0; kk < 8; kk++) {
            uint32_t Pa[4];
            Pa[0] = __float_as_uint(Ps[prow * 68 + kk * 8 + tig]);
            Pa[1] = __float_as_uint(Ps[(prow + 8) * 68 + kk * 8 + tig]);
            Pa[2] = __float_as_uint(Ps[prow * 68 + kk * 8 + tig + 4]);
            Pa[3] = __float_as_uint(Ps[(prow + 8) * 68 + kk * 8 + tig + 4]);
            uint32_t Vf[8][2];
#pragma unroll
            for (int n = 0; n < 8; n++) {
                Vf[n][0] = __float_as_uint(Vs[(kk * 8 + tig) * 68 + n * 8 + gid]);
                Vf[n][1] = __float_as_uint(Vs[(kk * 8 + tig + 4) * 68 + n * 8 + gid]);
            }
#pragma unroll
            for (int n = 0; n < 8; n++) mma8(O[n], Pa, Vf[n]);
        }
    }

    // ---- epilogue: reduce row-sums over the quad, normalize, write g_ao
    lsum0 += __shfl_xor_sync(0xffffffffu, lsum0, 1);
    lsum0 += __shfl_xor_sync(0xffffffffu, lsum0, 2);
    lsum1 += __shfl_xor_sync(0xffffffffu, lsum1, 1);
    lsum1 += __shfl_xor_sync(0xffffffffu, lsum1, 2);
    const float inv0 = 1.0f / lsum0, inv1 = 1.0f / lsum1;
    float* dst = g_ao + ((size_t)b * 2048 + qt * 64 + w * 16) * 768 + h * 64;
#pragma unroll
    for (int n = 0; n < 8; n++) {
        const int c0 = n * 8 + tig * 2;
        *(float2*)&dst[gid * 768 + c0] = make_float2(O[n][0] * inv0, O[n][1] * inv0);
        *(float2*)&dst[(gid + 8) * 768 + c0] = make_float2(O[n][2] * inv1, O[n][3] * inv1);
    }
}

// =============================================================================
// Kernel 3: out projection (validated R3, unchanged)
// =============================================================================
__global__ __launch_bounds__(256) void proj_gemm(const float* __restrict__ W,
                                                 const float* __restrict__ Bv,
                                                 float* __restrict__ out) {
    __shared__ float As[8][128];
    __shared__ float Bs[8][128];
    const int tid = threadIdx.x;
    const int bM = blockIdx.y * 128, bN = blockIdx.x * 128;
    const int aRow = tid >> 1, aCol = (tid & 1) * 4;
    const int bRow = tid >> 5, bCol = (tid & 31) * 4;
    const int ty = tid >> 4, tx = tid & 15;

    float acc[8][8];
#pragma unroll
    for (int i = 0; i < 8; i++)
#pragma unroll
        for (int j = 0; j < 8; j++) acc[i][j] = 0.f;

    const float* Aptr = g_ao + (size_t)(bM + aRow) * 768 + aCol;
    const float* Bptr = W + bRow * 768 + bN + bCol;

    for (int k0 = 0; k0 < 768; k0 += 8) {
        float4 a = *(const float4*)(Aptr + k0);
        float4 bv = *(const float4*)(Bptr + (size_t)k0 * 768);
        As[aCol + 0][aRow] = a.x; As[aCol + 1][aRow] = a.y;
        As[aCol + 2][aRow] = a.z; As[aCol + 3][aRow] = a.w;
        *(float4*)&Bs[bRow][bCol] = bv;
        __syncthreads();
#pragma unroll
        for (int kk = 0; kk < 8; kk++) {
            float ar[8], br[8];
            *(float4*)&ar[0] = *(const float4*)&As[kk][ty * 8];
            *(float4*)&ar[4] = *(const float4*)&As[kk][ty * 8 + 4];
            *(float4*)&br[0] = *(const float4*)&Bs[kk][tx * 8];
            *(float4*)&br[4] = *(const float4*)&Bs[kk][tx * 8 + 4];
#pragma unroll
            for (int i = 0; i < 8; i++)
#pragma unroll
                for (int j = 0; j < 8; j++) acc[i][j] += ar[i] * br[j];
        }
        __syncthreads();
    }

    const int col0 = bN + tx * 8;
    float bb[8];
#pragma unroll
    for (int j = 0; j < 8; j++) bb[j] = Bv[col0 + j];
#pragma unroll
    for (int i = 0; i < 8; i++) {
        int row = bM + ty * 8 + i;
        float* p = out + (size_t)row * 768 + col0;
        *(float4*)p = make_float4(acc[i][0] + bb[0], acc[i][1] + bb[1],
                                  acc[i][2] + bb[2], acc[i][3] + bb[3]);
        *(float4*)(p + 4) = make_float4(acc[i][4] + bb[4], acc[i][5] + bb[5],
                                        acc[i][6] + bb[6], acc[i][7] + bb[7]);
    }
}

// =============================================================================
extern "C" void kernel_launch(void* const* d_in, const int* in_sizes, int n_in,
                              void* d_out, int out_size) {
    const float* x         = (const float*)d_in[0];
    const int* dist        = (const int*)d_in[1];
    const unsigned int* mk = (const unsigned int*)d_in[2];
    const float* qkv_w     = (const float*)d_in[3];
    const float* qkv_b     = (const float*)d_in[4];
    const float* out_w     = (const float*)d_in[5];
    const float* out_b     = (const float*)d_in[6];
    const float* bt        = (const float*)d_in[7];
    float* out             = (float*)d_out;

    mask_prep<<<1, 256>>>(mk);
    dist_pack<<<4096, 256>>>(dist);

    dim3 g1(18, 32);
    qkv_gemm<<<g1, 256>>>(x, qkv_w, qkv_b);

    cudaFuncSetAttribute(attn_mma, cudaFuncAttributeMaxDynamicSharedMemorySize, ATTN_SMEM);
    dim3 g2(32, 12, 2);
    attn_mma<<<g2, 128, ATTN_SMEM>>>(bt);

    dim3 g3(6, 32);
    proj_gemm<<<g3, 256>>>(out_w, out_b, out);
}

// round 8
// speedup vs baseline: 1.9909x; 1.3877x over previous
#include <cuda_runtime.h>
#include <cstdint>

// ---------------- scratch (allocation-free rule: __device__ globals) ----------
// g_q/g_k/g_v : [B,H,N,64]  (tf32-rounded; q pre-scaled by 0.125)   g_ao : [B,N,768]
__device__ float g_q[2 * 12 * 2048 * 64];
__device__ float g_k[2 * 12 * 2048 * 64];
__device__ float g_v[2 * 12 * 2048 * 64];
__device__ float g_ao[2 * 2048 * 768];
__device__ float g_mneg[2 * 2048];                  // 0 or -1e30 per key
__device__ unsigned char g_dist8[2 * 2048 * 2048];  // clipped dist, 1 byte

__device__ __forceinline__ float to_tf32(float x) {
    float r;
    asm("cvt.rna.tf32.f32 %0, %1;" : "=f"(r) : "f"(x));
    return r;
}
// mma.sync m16n8k8 tf32 (sm_80+ path; validated R6)
__device__ __forceinline__ void mma8(float* c, const uint32_t* a, const uint32_t* b) {
    asm("mma.sync.aligned.m16n8k8.row.col.f32.tf32.tf32.f32 "
        "{%0,%1,%2,%3},{%4,%5,%6,%7},{%8,%9},{%0,%1,%2,%3};"
        : "+f"(c[0]), "+f"(c[1]), "+f"(c[2]), "+f"(c[3])
        : "r"(a[0]), "r"(a[1]), "r"(a[2]), "r"(a[3]), "r"(b[0]), "r"(b[1]));
}

// =============================================================================
// Kernel 0a: mask dtype sniffer + conversion (validated R3)
// =============================================================================
__global__ void mask_prep(const unsigned int* __restrict__ mw) {
    const int tid = threadIdx.x;
    int ok_int = 1, ok_flt = 1;
    for (int i = tid; i < 1024; i += 256) {
        unsigned int v = mw[i];
        if (v != 0u && v != 1u) ok_int = 0;
        if (v != 0u && v != 0x3F800000u) ok_flt = 0;
    }
    ok_int = __syncthreads_and(ok_int);
    ok_flt = __syncthreads_and(ok_flt);
    if (ok_int) {
        const int* m = (const int*)mw;
        for (int i = tid; i < 4096; i += 256) g_mneg[i] = m[i] ? -1e30f : 0.0f;
    } else if (ok_flt) {
        const float* m = (const float*)mw;
        for (int i = tid; i < 4096; i += 256) g_mneg[i] = (m[i] != 0.0f) ? -1e30f : 0.0f;
    } else {
        const unsigned char* m = (const unsigned char*)mw;
        for (int i = tid; i < 4096; i += 256) g_mneg[i] = m[i] ? -1e30f : 0.0f;
    }
}

// =============================================================================
// Kernel 0b: pack dist int32 -> clipped uint8
// =============================================================================
__global__ void dist_pack(const int* __restrict__ dist) {
    size_t i = ((size_t)blockIdx.x * 256 + threadIdx.x) * 8;
    int4 a = *(const int4*)(dist + i);
    int4 b = *(const int4*)(dist + i + 4);
    unsigned c0 = (unsigned)min(max(a.x, 0), 31) | ((unsigned)min(max(a.y, 0), 31) << 8) |
                  ((unsigned)min(max(a.z, 0), 31) << 16) | ((unsigned)min(max(a.w, 0), 31) << 24);
    unsigned c1 = (unsigned)min(max(b.x, 0), 31) | ((unsigned)min(max(b.y, 0), 31) << 8) |
                  ((unsigned)min(max(b.z, 0), 31) << 16) | ((unsigned)min(max(b.w, 0), 31) << 24);
    *(uint2*)(g_dist8 + i) = make_uint2(c0, c1);
}

// =============================================================================
// Kernel 1: tf32 tensor-core GEMM used for both projections.
//   C[4096, N] = tf32(A[4096,768]) @ tf32(W[768,N]) + b
// 128x128 tile, BK=16, 256 threads = 8 warps, warp tile 64x32 (4x4 m16n8).
// mode 0: A = x, scatter to g_q/g_k/g_v (tf32-rounds, Q*0.125).
// mode 1: A = g_ao (device symbol resolved IN DEVICE CODE — R7 bug was passing
//         g_ao as a host-side kernel argument, which is the host shadow addr).
// =============================================================================
__global__ __launch_bounds__(256) void gemm_tc(const float* __restrict__ A,
                                               const float* __restrict__ W,
                                               const float* __restrict__ Bv,
                                               float* __restrict__ outp,
                                               int N, int mode) {
    if (mode == 1) A = g_ao;  // FIX(R7): device-side symbol reference
    __shared__ float As[128][20];
    __shared__ float Bs[16][136];
    const int tid = threadIdx.x, w = tid >> 5, l = tid & 31;
    const int gid = l >> 2, tig = l & 3;
    const int wm = w >> 2, wn = w & 3;   // 2 x 4 warp grid
    const int bM = blockIdx.y * 128, bN = blockIdx.x * 128;

    float acc[4][4][4];
#pragma unroll
    for (int mi = 0; mi < 4; mi++)
#pragma unroll
        for (int ni = 0; ni < 4; ni++)
#pragma unroll
            for (int j = 0; j < 4; j++) acc[mi][ni][j] = 0.f;

    const int ar = tid >> 1, ac = (tid & 1) * 8;
    const int br = tid >> 4, bc = (tid & 15) * 8;
    const float* Ap = A + (size_t)(bM + ar) * 768 + ac;
    const float* Bp = W + (size_t)br * N + bN + bc;

    for (int k0 = 0; k0 < 768; k0 += 16) {
        float4 av0 = *(const float4*)(Ap + k0);
        float4 av1 = *(const float4*)(Ap + k0 + 4);
        float4 bv0 = *(const float4*)(Bp + (size_t)k0 * N);
        float4 bv1 = *(const float4*)(Bp + (size_t)k0 * N + 4);
        __syncthreads();  // previous tile fully consumed
        As[ar][ac + 0] = to_tf32(av0.x); As[ar][ac + 1] = to_tf32(av0.y);
        As[ar][ac + 2] = to_tf32(av0.z); As[ar][ac + 3] = to_tf32(av0.w);
        As[ar][ac + 4] = to_tf32(av1.x); As[ar][ac + 5] = to_tf32(av1.y);
        As[ar][ac + 6] = to_tf32(av1.z); As[ar][ac + 7] = to_tf32(av1.w);
        Bs[br][bc + 0] = to_tf32(bv0.x); Bs[br][bc + 1] = to_tf32(bv0.y);
        Bs[br][bc + 2] = to_tf32(bv0.z); Bs[br][bc + 3] = to_tf32(bv0.w);
        Bs[br][bc + 4] = to_tf32(bv1.x); Bs[br][bc + 5] = to_tf32(bv1.y);
        Bs[br][bc + 6] = to_tf32(bv1.z); Bs[br][bc + 7] = to_tf32(bv1.w);
        __syncthreads();

#pragma unroll
        for (int kk = 0; kk < 2; kk++) {
            const int kb = kk * 8;
            uint32_t Af[4][4], Bf[4][2];
#pragma unroll
            for (int mi = 0; mi < 4; mi++) {
                const int m0 = wm * 64 + mi * 16;
                Af[mi][0] = __float_as_uint(As[m0 + gid][kb + tig]);
                Af[mi][1] = __float_as_uint(As[m0 + gid + 8][kb + tig]);
                Af[mi][2] = __float_as_uint(As[m0 + gid][kb + tig + 4]);
                Af[mi][3] = __float_as_uint(As[m0 + gid + 8][kb + tig + 4]);
            }
#pragma unroll
            for (int ni = 0; ni < 4; ni++) {
                const int n0 = wn * 32 + ni * 8 + gid;
                Bf[ni][0] = __float_as_uint(Bs[kb + tig][n0]);
                Bf[ni][1] = __float_as_uint(Bs[kb + tig + 4][n0]);
            }
#pragma unroll
            for (int mi = 0; mi < 4; mi++)
#pragma unroll
                for (int ni = 0; ni < 4; ni++) mma8(acc[mi][ni], Af[mi], Bf[ni]);
        }
    }

    // ---- epilogue
#pragma unroll
    for (int ni = 0; ni < 4; ni++) {
        const int col0 = bN + wn * 32 + ni * 8 + tig * 2;
        const float b0 = Bv[col0], b1 = Bv[col0 + 1];
        if (mode == 0) {
            // scatter to g_q/g_k/g_v; a float2 never straddles a 64/768 boundary
            const int which = col0 / 768;
            const int rem = col0 % 768;
            const int hh = rem / 64, hd0 = rem % 64;
            float* dst = (which == 0) ? g_q : (which == 1 ? g_k : g_v);
            const float qs = (which == 0) ? 0.125f : 1.0f;
#pragma unroll
            for (int mi = 0; mi < 4; mi++) {
                const int row = bM + wm * 64 + mi * 16 + gid;
                const int bidx = row >> 11, n = row & 2047;
                float* p = dst + ((((size_t)bidx * 12 + hh) * 2048 + n) * 64 + hd0);
                *(float2*)p = make_float2(to_tf32((acc[mi][ni][0] + b0) * qs),
                                          to_tf32((acc[mi][ni][1] + b1) * qs));
                const int row2 = row + 8;
                const int bidx2 = row2 >> 11, n2 = row2 & 2047;
                float* p2 = dst + ((((size_t)bidx2 * 12 + hh) * 2048 + n2) * 64 + hd0);
                *(float2*)p2 = make_float2(to_tf32((acc[mi][ni][2] + b0) * qs),
                                           to_tf32((acc[mi][ni][3] + b1) * qs));
            }
        } else {
#pragma unroll
            for (int mi = 0; mi < 4; mi++) {
                const int row = bM + wm * 64 + mi * 16 + gid;
                *(float2*)(outp + (size_t)row * 768 + col0) =
                    make_float2(acc[mi][ni][0] + b0, acc[mi][ni][1] + b1);
                *(float2*)(outp + (size_t)(row + 8) * 768 + col0) =
                    make_float2(acc[mi][ni][2] + b0, acc[mi][ni][3] + b1);
            }
        }
    }
}

// =============================================================================
// Kernel 2: tf32 mma.sync flash attention (validated R6, unchanged)
// =============================================================================
static constexpr int KS_OFF = 0;             // [64][68] f32 = 17408 B
static constexpr int VS_OFF = 17408;         // [64][68] f32
static constexpr int PS_OFF = 34816;         // [64][68] f32
static constexpr int DS_OFF = 52224;         // [64][64] u8 = 4096 B
static constexpr int BT_OFF = 56320;         // 32 f32
static constexpr int MNG_OFF = 56448;        // 64 f32
static constexpr int ATTN_SMEM = 56704;

__global__ __launch_bounds__(128) void attn_mma(const float* __restrict__ bias_table) {
    extern __shared__ char smem[];
    float* Ks = (float*)(smem + KS_OFF);
    float* Vs = (float*)(smem + VS_OFF);
    float* Ps = (float*)(smem + PS_OFF);
    unsigned char* Ds = (unsigned char*)(smem + DS_OFF);
    float* btc = (float*)(smem + BT_OFF);
    float* mng = (float*)(smem + MNG_OFF);

    const int tid = threadIdx.x, w = tid >> 5, l = tid & 31;
    const int gid = l >> 2, tig = l & 3;
    const int qt = blockIdx.x, h = blockIdx.y, b = blockIdx.z;
    const size_t bh = (size_t)b * 12 + h;

    uint32_t Qa[8][4];
    {
        const float* qb = g_q + ((bh * 2048) + qt * 64 + w * 16) * 64;
#pragma unroll
        for (int s = 0; s < 8; s++) {
            Qa[s][0] = __float_as_uint(qb[gid * 64 + s * 8 + tig]);
            Qa[s][1] = __float_as_uint(qb[(gid + 8) * 64 + s * 8 + tig]);
            Qa[s][2] = __float_as_uint(qb[gid * 64 + s * 8 + tig + 4]);
            Qa[s][3] = __float_as_uint(qb[(gid + 8) * 64 + s * 8 + tig + 4]);
        }
    }
    if (tid < 32) btc[tid] = bias_table[tid * 12 + h];

    float O[8][4];
#pragma unroll
    for (int n = 0; n < 8; n++)
#pragma unroll
        for (int j = 0; j < 4; j++) O[n][j] = 0.f;
    float lsum0 = 0.f, lsum1 = 0.f;

    const int row = tid >> 1, half = tid & 1;

    for (int kt = 0; kt < 32; kt++) {
        __syncthreads();
        {
            const float* kr = g_k + (bh * 2048 + kt * 64 + row) * 64 + half * 32;
            const float* vr = g_v + (bh * 2048 + kt * 64 + row) * 64 + half * 32;
            float* kd = Ks + row * 68 + half * 32;
            float* vd = Vs + row * 68 + half * 32;
#pragma unroll
            for (int c = 0; c < 8; c++) {
                *(float4*)(kd + c * 4) = *(const float4*)(kr + c * 4);
                *(float4*)(vd + c * 4) = *(const float4*)(vr + c * 4);
            }
            const unsigned char* dr =
                g_dist8 + ((size_t)(b * 2048 + qt * 64 + row)) * 2048 + kt * 64 + half * 32;
            *(uint4*)(Ds + row * 64 + half * 32) = *(const uint4*)dr;
            *(uint4*)(Ds + row * 64 + half * 32 + 16) = *(const uint4*)(dr + 16);
        }
        if (tid < 64) mng[tid] = g_mneg[b * 2048 + kt * 64 + tid];
        __syncthreads();

        float S[8][4];
#pragma unroll
        for (int n = 0; n < 8; n++)
#pragma unroll
            for (int j = 0; j < 4; j++) S[n][j] = 0.f;
#pragma unroll
        for (int s = 0; s < 8; s++) {
            uint32_t Bf[8][2];
#pragma unroll
            for (int n = 0; n < 8; n++) {
                Bf[n][0] = __float_as_uint(Ks[(n * 8 + gid) * 68 + s * 8 + tig]);
                Bf[n][1] = __float_as_uint(Ks[(n * 8 + gid) * 68 + s * 8 + tig + 4]);
            }
#pragma unroll
            for (int n = 0; n < 8; n++) mma8(S[n], Qa[s], Bf[n]);
        }

        const unsigned char* d0p = Ds + (w * 16 + gid) * 64;
        const unsigned char* d1p = Ds + (w * 16 + gid + 8) * 64;
        const int prow = w * 16 + gid;
#pragma unroll
        for (int n = 0; n < 8; n++) {
            const int c0 = n * 8 + tig * 2;
            const float mg0 = mng[c0], mg1 = mng[c0 + 1];
            float p00 = to_tf32(__expf(S[n][0] + btc[d0p[c0]] + mg0));
            float p01 = to_tf32(__expf(S[n][1] + btc[d0p[c0 + 1]] + mg1));
            float p10 = to_tf32(__expf(S[n][2] + btc[d1p[c0]] + mg0));
            float p11 = to_tf32(__expf(S[n][3] + btc[d1p[c0 + 1]] + mg1));
            lsum0 += p00 + p01;
            lsum1 += p10 + p11;
            *(float2*)&Ps[prow * 68 + c0] = make_float2(p00, p01);
            *(float2*)&Ps[(prow + 8) * 68 + c0] = make_float2(p10, p11);
        }
        __syncwarp();

#pragma unroll
        for (int kk = 0; kk < 8; kk++) {
            uint32_t Pa[4];
            Pa[0] = __float_as_uint(Ps[prow * 68 + kk * 8 + tig]);
            Pa[1] = __float_as_uint(Ps[(prow + 8) * 68 + kk * 8 + tig]);
            Pa[2] = __float_as_uint(Ps[prow * 68 + kk * 8 + tig + 4]);
            Pa[3] = __float_as_uint(Ps[(prow + 8) * 68 + kk * 8 + tig + 4]);
            uint32_t Vf[8][2];
#pragma unroll
            for (int n = 0; n < 8; n++) {
                Vf[n][0] = __float_as_uint(Vs[(kk * 8 + tig) * 68 + n * 8 + gid]);
                Vf[n][1] = __float_as_uint(Vs[(kk * 8 + tig + 4) * 68 + n * 8 + gid]);
            }
#pragma unroll
            for (int n = 0; n < 8; n++) mma8(O[n], Pa, Vf[n]);
        }
    }

    lsum0 += __shfl_xor_sync(0xffffffffu, lsum0, 1);
    lsum0 += __shfl_xor_sync(0xffffffffu, lsum0, 2);
    lsum1 += __shfl_xor_sync(0xffffffffu, lsum1, 1);
    lsum1 += __shfl_xor_sync(0xffffffffu, lsum1, 2);
    const float inv0 = 1.0f / lsum0, inv1 = 1.0f / lsum1;
    float* dst = g_ao + ((size_t)b * 2048 + qt * 64 + w * 16) * 768 + h * 64;
#pragma unroll
    for (int n = 0; n < 8; n++) {
        const int c0 = n * 8 + tig * 2;
        *(float2*)&dst[gid * 768 + c0] = make_float2(O[n][0] * inv0, O[n][1] * inv0);
        *(float2*)&dst[(gid + 8) * 768 + c0] = make_float2(O[n][2] * inv1, O[n][3] * inv1);
    }
}

// =============================================================================
extern "C" void kernel_launch(void* const* d_in, const int* in_sizes, int n_in,
                              void* d_out, int out_size) {
    const float* x         = (const float*)d_in[0];
    const int* dist        = (const int*)d_in[1];
    const unsigned int* mk = (const unsigned int*)d_in[2];
    const float* qkv_w     = (const float*)d_in[3];
    const float* qkv_b     = (const float*)d_in[4];
    const float* out_w     = (const float*)d_in[5];
    const float* out_b     = (const float*)d_in[6];
    const float* bt        = (const float*)d_in[7];
    float* out             = (float*)d_out;

    mask_prep<<<1, 256>>>(mk);
    dist_pack<<<4096, 256>>>(dist);

    dim3 g1(18, 32);
    gemm_tc<<<g1, 256>>>(x, qkv_w, qkv_b, nullptr, 2304, 0);

    cudaFuncSetAttribute(attn_mma, cudaFuncAttributeMaxDynamicSharedMemorySize, ATTN_SMEM);
    dim3 g2(32, 12, 2);
    attn_mma<<<g2, 128, ATTN_SMEM>>>(bt);

    dim3 g3(6, 32);
    gemm_tc<<<g3, 256>>>(nullptr, out_w, out_b, out, 768, 1);
}

// round 9
// speedup vs baseline: 3.2728x; 1.6439x over previous
#include <cuda_runtime.h>
#include <cstdint>

// ---------------- scratch (allocation-free rule: __device__ globals) ----------
// g_q/g_k/g_v : [B,H,N,64] (tf32-rounded; q pre-scaled by 0.125)
// g_vt : [B,H,64,N] (V transposed)   g_ao : [B,N,768]
__device__ float g_q[2 * 12 * 2048 * 64];
__device__ float g_k[2 * 12 * 2048 * 64];
__device__ float g_v[2 * 12 * 2048 * 64];
__device__ float g_vt[2 * 12 * 64 * 2048];
__device__ float g_ao[2 * 2048 * 768];
__device__ float g_mneg[2 * 2048];                  // 0 or -1e30 per key
__device__ unsigned char g_dist8[2 * 2048 * 2048];  // clipped dist, 1 byte

__device__ __forceinline__ float to_tf32(float x) {
    float r;
    asm("cvt.rna.tf32.f32 %0, %1;" : "=f"(r) : "f"(x));
    return r;
}
__device__ __forceinline__ void mma8(float* c, const uint32_t* a, const uint32_t* b) {
    asm("mma.sync.aligned.m16n8k8.row.col.f32.tf32.tf32.f32 "
        "{%0,%1,%2,%3},{%4,%5,%6,%7},{%8,%9},{%0,%1,%2,%3};"
        : "+f"(c[0]), "+f"(c[1]), "+f"(c[2]), "+f"(c[3])
        : "r"(a[0]), "r"(a[1]), "r"(a[2]), "r"(a[3]), "r"(b[0]), "r"(b[1]));
}
__device__ __forceinline__ uint32_t smem_u32(const void* p) {
    uint32_t a;
    asm("{ .reg .u64 t; cvta.to.shared.u64 t, %1; cvt.u32.u64 %0, t; }" : "=r"(a) : "l"(p));
    return a;
}
// tf32 fragments via b16 ldmatrix: lane l <- (row l/4, col l%4) per 8x4-tf32 tile
__device__ __forceinline__ void ldsm4(uint32_t* r, uint32_t addr) {
    asm volatile("ldmatrix.sync.aligned.m8n8.x4.shared.b16 {%0,%1,%2,%3}, [%4];"
                 : "=r"(r[0]), "=r"(r[1]), "=r"(r[2]), "=r"(r[3]) : "r"(addr));
}
__device__ __forceinline__ void cpa16(uint32_t saddr, const void* g) {
    asm volatile("cp.async.cg.shared.global [%0], [%1], 16;" :: "r"(saddr), "l"(g));
}
#define CP_COMMIT() asm volatile("cp.async.commit_group;" ::: "memory")
#define CP_WAIT0()  asm volatile("cp.async.wait_group 0;" ::: "memory")

// =============================================================================
// Kernel 0a: mask dtype sniffer + conversion (validated R3)
// =============================================================================
__global__ void mask_prep(const unsigned int* __restrict__ mw) {
    const int tid = threadIdx.x;
    int ok_int = 1, ok_flt = 1;
    for (int i = tid; i < 1024; i += 256) {
        unsigned int v = mw[i];
        if (v != 0u && v != 1u) ok_int = 0;
        if (v != 0u && v != 0x3F800000u) ok_flt = 0;
    }
    ok_int = __syncthreads_and(ok_int);
    ok_flt = __syncthreads_and(ok_flt);
    if (ok_int) {
        const int* m = (const int*)mw;
        for (int i = tid; i < 4096; i += 256) g_mneg[i] = m[i] ? -1e30f : 0.0f;
    } else if (ok_flt) {
        const float* m = (const float*)mw;
        for (int i = tid; i < 4096; i += 256) g_mneg[i] = (m[i] != 0.0f) ? -1e30f : 0.0f;
    } else {
        const unsigned char* m = (const unsigned char*)mw;
        for (int i = tid; i < 4096; i += 256) g_mneg[i] = m[i] ? -1e30f : 0.0f;
    }
}

// =============================================================================
// Kernel 0b: pack dist int32 -> clipped uint8 (validated R6)
// =============================================================================
__global__ void dist_pack(const int* __restrict__ dist) {
    size_t i = ((size_t)blockIdx.x * 256 + threadIdx.x) * 8;
    int4 a = *(const int4*)(dist + i);
    int4 b = *(const int4*)(dist + i + 4);
    unsigned c0 = (unsigned)min(max(a.x, 0), 31) | ((unsigned)min(max(a.y, 0), 31) << 8) |
                  ((unsigned)min(max(a.z, 0), 31) << 16) | ((unsigned)min(max(a.w, 0), 31) << 24);
    unsigned c1 = (unsigned)min(max(b.x, 0), 31) | ((unsigned)min(max(b.y, 0), 31) << 8) |
                  ((unsigned)min(max(b.z, 0), 31) << 16) | ((unsigned)min(max(b.w, 0), 31) << 24);
    *(uint2*)(g_dist8 + i) = make_uint2(c0, c1);
}

// =============================================================================
// Kernel 1: tf32 tensor-core GEMM, both projections (validated R8)
// =============================================================================
__global__ __launch_bounds__(256) void gemm_tc(const float* __restrict__ A,
                                               const float* __restrict__ W,
                                               const float* __restrict__ Bv,
                                               float* __restrict__ outp,
                                               int N, int mode) {
    if (mode == 1) A = g_ao;  // device-side symbol reference (R7 fix)
    __shared__ float As[128][20];
    __shared__ float Bs[16][136];
    const int tid = threadIdx.x, w = tid >> 5, l = tid & 31;
    const int gid = l >> 2, tig = l & 3;
    const int wm = w >> 2, wn = w & 3;
    const int bM = blockIdx.y * 128, bN = blockIdx.x * 128;

    float acc[4][4][4];
#pragma unroll
    for (int mi = 0; mi < 4; mi++)
#pragma unroll
        for (int ni = 0; ni < 4; ni++)
#pragma unroll
            for (int j = 0; j < 4; j++) acc[mi][ni][j] = 0.f;

    const int ar = tid >> 1, ac = (tid & 1) * 8;
    const int br = tid >> 4, bc = (tid & 15) * 8;
    const float* Ap = A + (size_t)(bM + ar) * 768 + ac;
    const float* Bp = W + (size_t)br * N + bN + bc;

    for (int k0 = 0; k0 < 768; k0 += 16) {
        float4 av0 = *(const float4*)(Ap + k0);
        float4 av1 = *(const float4*)(Ap + k0 + 4);
        float4 bv0 = *(const float4*)(Bp + (size_t)k0 * N);
        float4 bv1 = *(const float4*)(Bp + (size_t)k0 * N + 4);
        __syncthreads();
        As[ar][ac + 0] = to_tf32(av0.x); As[ar][ac + 1] = to_tf32(av0.y);
        As[ar][ac + 2] = to_tf32(av0.z); As[ar][ac + 3] = to_tf32(av0.w);
        As[ar][ac + 4] = to_tf32(av1.x); As[ar][ac + 5] = to_tf32(av1.y);
        As[ar][ac + 6] = to_tf32(av1.z); As[ar][ac + 7] = to_tf32(av1.w);
        Bs[br][bc + 0] = to_tf32(bv0.x); Bs[br][bc + 1] = to_tf32(bv0.y);
        Bs[br][bc + 2] = to_tf32(bv0.z); Bs[br][bc + 3] = to_tf32(bv0.w);
        Bs[br][bc + 4] = to_tf32(bv1.x); Bs[br][bc + 5] = to_tf32(bv1.y);
        Bs[br][bc + 6] = to_tf32(bv1.z); Bs[br][bc + 7] = to_tf32(bv1.w);
        __syncthreads();

#pragma unroll
        for (int kk = 0; kk < 2; kk++) {
            const int kb = kk * 8;
            uint32_t Af[4][4], Bf[4][2];
#pragma unroll
            for (int mi = 0; mi < 4; mi++) {
                const int m0 = wm * 64 + mi * 16;
                Af[mi][0] = __float_as_uint(As[m0 + gid][kb + tig]);
                Af[mi][1] = __float_as_uint(As[m0 + gid + 8][kb + tig]);
                Af[mi][2] = __float_as_uint(As[m0 + gid][kb + tig + 4]);
                Af[mi][3] = __float_as_uint(As[m0 + gid + 8][kb + tig + 4]);
            }
#pragma unroll
            for (int ni = 0; ni < 4; ni++) {
                const int n0 = wn * 32 + ni * 8 + gid;
                Bf[ni][0] = __float_as_uint(Bs[kb + tig][n0]);
                Bf[ni][1] = __float_as_uint(Bs[kb + tig + 4][n0]);
            }
#pragma unroll
            for (int mi = 0; mi < 4; mi++)
#pragma unroll
                for (int ni = 0; ni < 4; ni++) mma8(acc[mi][ni], Af[mi], Bf[ni]);
        }
    }

#pragma unroll
    for (int ni = 0; ni < 4; ni++) {
        const int col0 = bN + wn * 32 + ni * 8 + tig * 2;
        const float b0 = Bv[col0], b1 = Bv[col0 + 1];
        if (mode == 0) {
            const int which = col0 / 768;
            const int rem = col0 % 768;
            const int hh = rem / 64, hd0 = rem % 64;
            float* dst = (which == 0) ? g_q : (which == 1 ? g_k : g_v);
            const float qs = (which == 0) ? 0.125f : 1.0f;
#pragma unroll
            for (int mi = 0; mi < 4; mi++) {
                const int row = bM + wm * 64 + mi * 16 + gid;
                const int bidx = row >> 11, n = row & 2047;
                float* p = dst + ((((size_t)bidx * 12 + hh) * 2048 + n) * 64 + hd0);
                *(float2*)p = make_float2(to_tf32((acc[mi][ni][0] + b0) * qs),
                                          to_tf32((acc[mi][ni][1] + b1) * qs));
                const int row2 = row + 8;
                const int bidx2 = row2 >> 11, n2 = row2 & 2047;
                float* p2 = dst + ((((size_t)bidx2 * 12 + hh) * 2048 + n2) * 64 + hd0);
                *(float2*)p2 = make_float2(to_tf32((acc[mi][ni][2] + b0) * qs),
                                           to_tf32((acc[mi][ni][3] + b1) * qs));
            }
        } else {
#pragma unroll
            for (int mi = 0; mi < 4; mi++) {
                const int row = bM + wm * 64 + mi * 16 + gid;
                *(float2*)(outp + (size_t)row * 768 + col0) =
                    make_float2(acc[mi][ni][0] + b0, acc[mi][ni][1] + b1);
                *(float2*)(outp + (size_t)(row + 8) * 768 + col0) =
                    make_float2(acc[mi][ni][2] + b0, acc[mi][ni][3] + b1);
            }
        }
    }
}

// =============================================================================
// Kernel 1b: transpose V -> g_vt [B,H,64,N]
// =============================================================================
__global__ __launch_bounds__(256) void v_transpose() {
    __shared__ float sm[64 * 65];
    const int n0 = blockIdx.x * 64;
    const int bh = blockIdx.y;
    const float* src = g_v + ((size_t)bh * 2048 + n0) * 64;
    for (int v = threadIdx.x; v < 1024; v += 256) {
        int i = v >> 4, d4 = (v & 15) << 2;
        float4 t = *(const float4*)(src + i * 64 + d4);
        sm[(d4 + 0) * 65 + i] = t.x; sm[(d4 + 1) * 65 + i] = t.y;
        sm[(d4 + 2) * 65 + i] = t.z; sm[(d4 + 3) * 65 + i] = t.w;
    }
    __syncthreads();
    float* dst = g_vt + (size_t)bh * 64 * 2048 + n0;
    for (int v = threadIdx.x; v < 1024; v += 256) {
        int d = v >> 4, j4 = (v & 15) << 2;
        *(float4*)(dst + (size_t)d * 2048 + j4) =
            make_float4(sm[d * 65 + j4], sm[d * 65 + j4 + 1],
                        sm[d * 65 + j4 + 2], sm[d * 65 + j4 + 3]);
    }
}

// =============================================================================
// Kernel 2: tf32 mma.sync flash attention, LDSM + cp.async edition.
// CTA = 128 queries (8 warps x 16 rows) x full key sweep (32 tiles of 64 keys).
// smem rows padded to 68 floats (272B: 16B-aligned, LDSM conflict-free).
// =============================================================================
static constexpr int KS_OFF = 0;              // K  [64 keys][68] f32 = 17408
static constexpr int VT_OFF = 17408;          // Vt [64 d][68]  f32 = 17408
static constexpr int DS_OFF = 34816;          // dist [128 q][64] u8 = 8192
static constexpr int MNG_OFF = 43008;         // 64 f32 = 256
static constexpr int PS_OFF = 43264;          // P [128 q][68] f32 = 34816
static constexpr int BT_OFF = 78080;          // 32 f32
static constexpr int ATTN_SMEM = 78208;

__global__ __launch_bounds__(256, 2) void attn_mma(const float* __restrict__ bias_table) {
    extern __shared__ char smem[];
    const uint32_t sb = smem_u32(smem);
    unsigned char* Ds = (unsigned char*)(smem + DS_OFF);
    float* mng = (float*)(smem + MNG_OFF);
    float* Ps = (float*)(smem + PS_OFF);
    float* btc = (float*)(smem + BT_OFF);

    const int tid = threadIdx.x, w = tid >> 5, l = tid & 31;
    const int gid = l >> 2, tig = l & 3;
    const int qt = blockIdx.x, h = blockIdx.y, b = blockIdx.z;
    const size_t bh = (size_t)b * 12 + h;

    // ---- Q fragments (register-resident)
    uint32_t Qa[8][4];
    {
        const float* qb = g_q + ((bh * 2048) + qt * 128 + w * 16) * 64;
#pragma unroll
        for (int s = 0; s < 8; s++) {
            Qa[s][0] = __float_as_uint(qb[gid * 64 + s * 8 + tig]);
            Qa[s][1] = __float_as_uint(qb[(gid + 8) * 64 + s * 8 + tig]);
            Qa[s][2] = __float_as_uint(qb[gid * 64 + s * 8 + tig + 4]);
            Qa[s][3] = __float_as_uint(qb[(gid + 8) * 64 + s * 8 + tig + 4]);
        }
    }
    if (tid < 32) btc[tid] = bias_table[tid * 12 + h];

    // ---- per-lane LDSM address bases
    // B-frag (K and Vt): r0/r1 = pair-row block 0, r2/r3 = block 1
    const uint32_t rowB = (l & 7) + ((l >> 4) & 1) * 8;
    const uint32_t colB = ((l >> 3) & 1) * 4;
    const uint32_t kbase = sb + KS_OFF + (rowB * 68 + colB) * 4;
    const uint32_t vbase = sb + VT_OFF + (rowB * 68 + colB) * 4;
    // A-frag (P): r0 rows0-7 lo, r1 rows8-15 lo, r2 rows0-7 hi, r3 rows8-15 hi
    const uint32_t prowA = (l & 7) + ((l >> 3) & 1) * 8;
    const uint32_t pcolA = ((l >> 4) & 1) * 4;
    const uint32_t pbase = sb + PS_OFF + ((w * 16 + prowA) * 68 + pcolA) * 4;

    float O[8][4];
#pragma unroll
    for (int n = 0; n < 8; n++)
#pragma unroll
        for (int j = 0; j < 4; j++) O[n][j] = 0.f;
    float lsum0 = 0.f, lsum1 = 0.f;

    const char* kgbase = (const char*)(g_k + (bh * 2048) * 64);
    const char* vgbase = (const char*)(g_vt + bh * 131072);
    const unsigned char* dgbase = g_dist8 + (size_t)(b * 2048 + qt * 128) * 2048;

    for (int kt = 0; kt < 32; kt++) {
        __syncthreads();  // everyone done with previous tile's smem
        // ---- cp.async staging: K(64x256B), Vt(64x256B), dist(128x64B), mask
        {
#pragma unroll
            for (int j = 0; j < 4; j++) {
                int c = tid + j * 256, r = c >> 4, o = (c & 15) * 16;
                cpa16(sb + KS_OFF + r * 272 + o, kgbase + ((size_t)(kt * 64 + r) * 256) + o);
            }
#pragma unroll
            for (int j = 0; j < 4; j++) {
                int c = tid + j * 256, r = c >> 4, o = (c & 15) * 16;
                cpa16(sb + VT_OFF + r * 272 + o, vgbase + ((size_t)r * 8192) + kt * 256 + o);
            }
#pragma unroll
            for (int j = 0; j < 2; j++) {
                int c = tid + j * 256, r = c >> 2, o = (c & 3) * 16;
                cpa16(sb + DS_OFF + r * 64 + o, dgbase + (size_t)r * 2048 + kt * 64 + o);
            }
            if (tid < 16) cpa16(sb + MNG_OFF + tid * 16, g_mneg + b * 2048 + kt * 64 + tid * 4);
        }
        CP_COMMIT();
        CP_WAIT0();
        __syncthreads();

        // ---- S = Q @ K^T : per s-step, 4 LDSM.x4 feed 8 mma
        float S[8][4];
#pragma unroll
        for (int n = 0; n < 8; n++)
#pragma unroll
            for (int j = 0; j < 4; j++) S[n][j] = 0.f;
#pragma unroll
        for (int s = 0; s < 8; s++) {
            uint32_t Bf[4][4];
#pragma unroll
            for (int p = 0; p < 4; p++) ldsm4(Bf[p], kbase + p * 4352 + s * 32);
#pragma unroll
            for (int p = 0; p < 4; p++) {
                mma8(S[2 * p], Qa[s], &Bf[p][0]);
                mma8(S[2 * p + 1], Qa[s], &Bf[p][2]);
            }
        }

        // ---- bias + mask + exp -> Ps
        const unsigned char* d0p = Ds + (w * 16 + gid) * 64;
        const unsigned char* d1p = Ds + (w * 16 + gid + 8) * 64;
        const int prow = w * 16 + gid;
#pragma unroll
        for (int n = 0; n < 8; n++) {
            const int c0 = n * 8 + tig * 2;
            const float mg0 = mng[c0], mg1 = mng[c0 + 1];
            float p00 = to_tf32(__expf(S[n][0] + btc[d0p[c0]] + mg0));
            float p01 = to_tf32(__expf(S[n][1] + btc[d0p[c0 + 1]] + mg1));
            float p10 = to_tf32(__expf(S[n][2] + btc[d1p[c0]] + mg0));
            float p11 = to_tf32(__expf(S[n][3] + btc[d1p[c0 + 1]] + mg1));
            lsum0 += p00 + p01;
            lsum1 += p10 + p11;
            *(float2*)&Ps[prow * 68 + c0] = make_float2(p00, p01);
            *(float2*)&Ps[(prow + 8) * 68 + c0] = make_float2(p10, p11);
        }
        __syncwarp();  // Ps rows warp-private; cross-lane LDSM below

        // ---- O += P @ V : per kk, 1+4 LDSM.x4 feed 8 mma
#pragma unroll
        for (int kk = 0; kk < 8; kk++) {
            uint32_t Pa[4];
            ldsm4(Pa, pbase + kk * 32);
            uint32_t Vf[4][4];
#pragma unroll
            for (int p = 0; p < 4; p++) ldsm4(Vf[p], vbase + p * 4352 + kk * 32);
#pragma unroll
            for (int p = 0; p < 4; p++) {
                mma8(O[2 * p], Pa, &Vf[p][0]);
                mma8(O[2 * p + 1], Pa, &Vf[p][2]);
            }
        }
    }

    // ---- epilogue: quad-reduce row sums, normalize, write g_ao
    lsum0 += __shfl_xor_sync(0xffffffffu, lsum0, 1);
    lsum0 += __shfl_xor_sync(0xffffffffu, lsum0, 2);
    lsum1 += __shfl_xor_sync(0xffffffffu, lsum1, 1);
    lsum1 += __shfl_xor_sync(0xffffffffu, lsum1, 2);
    const float inv0 = 1.0f / lsum0, inv1 = 1.0f / lsum1;
    float* dst = g_ao + ((size_t)b * 2048 + qt * 128 + w * 16) * 768 + h * 64;
#pragma unroll
    for (int n = 0; n < 8; n++) {
        const int c0 = n * 8 + tig * 2;
        *(float2*)&dst[gid * 768 + c0] = make_float2(O[n][0] * inv0, O[n][1] * inv0);
        *(float2*)&dst[(gid + 8) * 768 + c0] = make_float2(O[n][2] * inv1, O[n][3] * inv1);
    }
}

// =============================================================================
extern "C" void kernel_launch(void* const* d_in, const int* in_sizes, int n_in,
                              void* d_out, int out_size) {
    const float* x         = (const float*)d_in[0];
    const int* dist        = (const int*)d_in[1];
    const unsigned int* mk = (const unsigned int*)d_in[2];
    const float* qkv_w     = (const float*)d_in[3];
    const float* qkv_b     = (const float*)d_in[4];
    const float* out_w     = (const float*)d_in[5];
    const float* out_b     = (const float*)d_in[6];
    const float* bt        = (const float*)d_in[7];
    float* out             = (float*)d_out;

    mask_prep<<<1, 256>>>(mk);
    dist_pack<<<4096, 256>>>(dist);

    dim3 g1(18, 32);
    gemm_tc<<<g1, 256>>>(x, qkv_w, qkv_b, nullptr, 2304, 0);

    dim3 gt(32, 24);
    v_transpose<<<gt, 256>>>();

    cudaFuncSetAttribute(attn_mma, cudaFuncAttributeMaxDynamicSharedMemorySize, ATTN_SMEM);
    dim3 g2(16, 12, 2);
    attn_mma<<<g2, 256, ATTN_SMEM>>>(bt);

    dim3 g3(6, 32);
    gemm_tc<<<g3, 256>>>(nullptr, out_w, out_b, out, 768, 1);
}

// round 10
// speedup vs baseline: 3.4019x; 1.0395x over previous
#include <cuda_runtime.h>
#include <cstdint>

// ---------------- scratch (allocation-free rule: __device__ globals) ----------
// g_q/g_k/g_v : [B,H,N,64] (tf32-rounded; q pre-scaled by 0.125)
// g_vt : [B,H,64,N] (V transposed)   g_ao : [B,N,768]
__device__ float g_q[2 * 12 * 2048 * 64];
__device__ float g_k[2 * 12 * 2048 * 64];
__device__ float g_v[2 * 12 * 2048 * 64];
__device__ float g_vt[2 * 12 * 64 * 2048];
__device__ float g_ao[2 * 2048 * 768];
__device__ float g_mneg[2 * 2048];                  // 0 or -1e30 per key
__device__ unsigned char g_dist8[2 * 2048 * 2048];  // clipped dist, 1 byte

__device__ __forceinline__ float to_tf32(float x) {
    float r;
    asm("cvt.rna.tf32.f32 %0, %1;" : "=f"(r) : "f"(x));
    return r;
}
__device__ __forceinline__ void mma8(float* c, const uint32_t* a, const uint32_t* b) {
    asm("mma.sync.aligned.m16n8k8.row.col.f32.tf32.tf32.f32 "
        "{%0,%1,%2,%3},{%4,%5,%6,%7},{%8,%9},{%0,%1,%2,%3};"
        : "+f"(c[0]), "+f"(c[1]), "+f"(c[2]), "+f"(c[3])
        : "r"(a[0]), "r"(a[1]), "r"(a[2]), "r"(a[3]), "r"(b[0]), "r"(b[1]));
}
__device__ __forceinline__ uint32_t smem_u32(const void* p) {
    uint32_t a;
    asm("{ .reg .u64 t; cvta.to.shared.u64 t, %1; cvt.u32.u64 %0, t; }" : "=r"(a) : "l"(p));
    return a;
}
// tf32 fragments via b16 ldmatrix: lane l <- (row l/4, col l%4) per 8x4-tf32 tile
__device__ __forceinline__ void ldsm4(uint32_t* r, uint32_t addr) {
    asm volatile("ldmatrix.sync.aligned.m8n8.x4.shared.b16 {%0,%1,%2,%3}, [%4];"
                 : "=r"(r[0]), "=r"(r[1]), "=r"(r[2]), "=r"(r[3]) : "r"(addr));
}
__device__ __forceinline__ void cpa16(uint32_t saddr, const void* g) {
    asm volatile("cp.async.cg.shared.global [%0], [%1], 16;" :: "r"(saddr), "l"(g));
}
#define CP_COMMIT() asm volatile("cp.async.commit_group;" ::: "memory")
#define CP_WAIT0()  asm volatile("cp.async.wait_group 0;" ::: "memory")
#define CP_WAIT1()  asm volatile("cp.async.wait_group 1;" ::: "memory")

// =============================================================================
// Kernel 0a: mask dtype sniffer + conversion (validated R3)
// =============================================================================
__global__ void mask_prep(const unsigned int* __restrict__ mw) {
    const int tid = threadIdx.x;
    int ok_int = 1, ok_flt = 1;
    for (int i = tid; i < 1024; i += 256) {
        unsigned int v = mw[i];
        if (v != 0u && v != 1u) ok_int = 0;
        if (v != 0u && v != 0x3F800000u) ok_flt = 0;
    }
    ok_int = __syncthreads_and(ok_int);
    ok_flt = __syncthreads_and(ok_flt);
    if (ok_int) {
        const int* m = (const int*)mw;
        for (int i = tid; i < 4096; i += 256) g_mneg[i] = m[i] ? -1e30f : 0.0f;
    } else if (ok_flt) {
        const float* m = (const float*)mw;
        for (int i = tid; i < 4096; i += 256) g_mneg[i] = (m[i] != 0.0f) ? -1e30f : 0.0f;
    } else {
        const unsigned char* m = (const unsigned char*)mw;
        for (int i = tid; i < 4096; i += 256) g_mneg[i] = m[i] ? -1e30f : 0.0f;
    }
}

// =============================================================================
// Kernel 0b: pack dist int32 -> clipped uint8 (validated R6)
// =============================================================================
__global__ void dist_pack(const int* __restrict__ dist) {
    size_t i = ((size_t)blockIdx.x * 256 + threadIdx.x) * 8;
    int4 a = *(const int4*)(dist + i);
    int4 b = *(const int4*)(dist + i + 4);
    unsigned c0 = (unsigned)min(max(a.x, 0), 31) | ((unsigned)min(max(a.y, 0), 31) << 8) |
                  ((unsigned)min(max(a.z, 0), 31) << 16) | ((unsigned)min(max(a.w, 0), 31) << 24);
    unsigned c1 = (unsigned)min(max(b.x, 0), 31) | ((unsigned)min(max(b.y, 0), 31) << 8) |
                  ((unsigned)min(max(b.z, 0), 31) << 16) | ((unsigned)min(max(b.w, 0), 31) << 24);
    *(uint2*)(g_dist8 + i) = make_uint2(c0, c1);
}

// =============================================================================
// Kernel 1: tf32 tensor-core GEMM, both projections (validated R8)
// =============================================================================
__global__ __launch_bounds__(256) void gemm_tc(const float* __restrict__ A,
                                               const float* __restrict__ W,
                                               const float* __restrict__ Bv,
                                               float* __restrict__ outp,
                                               int N, int mode) {
    if (mode == 1) A = g_ao;  // device-side symbol reference (R7 fix)
    __shared__ float As[128][20];
    __shared__ float Bs[16][136];
    const int tid = threadIdx.x, w = tid >> 5, l = tid & 31;
    const int gid = l >> 2, tig = l & 3;
    const int wm = w >> 2, wn = w & 3;
    const int bM = blockIdx.y * 128, bN = blockIdx.x * 128;

    float acc[4][4][4];
#pragma unroll
    for (int mi = 0; mi < 4; mi++)
#pragma unroll
        for (int ni = 0; ni < 4; ni++)
#pragma unroll
            for (int j = 0; j < 4; j++) acc[mi][ni][j] = 0.f;

    const int ar = tid >> 1, ac = (tid & 1) * 8;
    const int br = tid >> 4, bc = (tid & 15) * 8;
    const float* Ap = A + (size_t)(bM + ar) * 768 + ac;
    const float* Bp = W + (size_t)br * N + bN + bc;

    for (int k0 = 0; k0 < 768; k0 += 16) {
        float4 av0 = *(const float4*)(Ap + k0);
        float4 av1 = *(const float4*)(Ap + k0 + 4);
        float4 bv0 = *(const float4*)(Bp + (size_t)k0 * N);
        float4 bv1 = *(const float4*)(Bp + (size_t)k0 * N + 4);
        __syncthreads();
        As[ar][ac + 0] = to_tf32(av0.x); As[ar][ac + 1] = to_tf32(av0.y);
        As[ar][ac + 2] = to_tf32(av0.z); As[ar][ac + 3] = to_tf32(av0.w);
        As[ar][ac + 4] = to_tf32(av1.x); As[ar][ac + 5] = to_tf32(av1.y);
        As[ar][ac + 6] = to_tf32(av1.z); As[ar][ac + 7] = to_tf32(av1.w);
        Bs[br][bc + 0] = to_tf32(bv0.x); Bs[br][bc + 1] = to_tf32(bv0.y);
        Bs[br][bc + 2] = to_tf32(bv0.z); Bs[br][bc + 3] = to_tf32(bv0.w);
        Bs[br][bc + 4] = to_tf32(bv1.x); Bs[br][bc + 5] = to_tf32(bv1.y);
        Bs[br][bc + 6] = to_tf32(bv1.z); Bs[br][bc + 7] = to_tf32(bv1.w);
        __syncthreads();

#pragma unroll
        for (int kk = 0; kk < 2; kk++) {
            const int kb = kk * 8;
            uint32_t Af[4][4], Bf[4][2];
#pragma unroll
            for (int mi = 0; mi < 4; mi++) {
                const int m0 = wm * 64 + mi * 16;
                Af[mi][0] = __float_as_uint(As[m0 + gid][kb + tig]);
                Af[mi][1] = __float_as_uint(As[m0 + gid + 8][kb + tig]);
                Af[mi][2] = __float_as_uint(As[m0 + gid][kb + tig + 4]);
                Af[mi][3] = __float_as_uint(As[m0 + gid + 8][kb + tig + 4]);
            }
#pragma unroll
            for (int ni = 0; ni < 4; ni++) {
                const int n0 = wn * 32 + ni * 8 + gid;
                Bf[ni][0] = __float_as_uint(Bs[kb + tig][n0]);
                Bf[ni][1] = __float_as_uint(Bs[kb + tig + 4][n0]);
            }
#pragma unroll
            for (int mi = 0; mi < 4; mi++)
#pragma unroll
                for (int ni = 0; ni < 4; ni++) mma8(acc[mi][ni], Af[mi], Bf[ni]);
        }
    }

#pragma unroll
    for (int ni = 0; ni < 4; ni++) {
        const int col0 = bN + wn * 32 + ni * 8 + tig * 2;
        const float b0 = Bv[col0], b1 = Bv[col0 + 1];
        if (mode == 0) {
            const int which = col0 / 768;
            const int rem = col0 % 768;
            const int hh = rem / 64, hd0 = rem % 64;
            float* dst = (which == 0) ? g_q : (which == 1 ? g_k : g_v);
            const float qs = (which == 0) ? 0.125f : 1.0f;
#pragma unroll
            for (int mi = 0; mi < 4; mi++) {
                const int row = bM + wm * 64 + mi * 16 + gid;
                const int bidx = row >> 11, n = row & 2047;
                float* p = dst + ((((size_t)bidx * 12 + hh) * 2048 + n) * 64 + hd0);
                *(float2*)p = make_float2(to_tf32((acc[mi][ni][0] + b0) * qs),
                                          to_tf32((acc[mi][ni][1] + b1) * qs));
                const int row2 = row + 8;
                const int bidx2 = row2 >> 11, n2 = row2 & 2047;
                float* p2 = dst + ((((size_t)bidx2 * 12 + hh) * 2048 + n2) * 64 + hd0);
                *(float2*)p2 = make_float2(to_tf32((acc[mi][ni][2] + b0) * qs),
                                           to_tf32((acc[mi][ni][3] + b1) * qs));
            }
        } else {
#pragma unroll
            for (int mi = 0; mi < 4; mi++) {
                const int row = bM + wm * 64 + mi * 16 + gid;
                *(float2*)(outp + (size_t)row * 768 + col0) =
                    make_float2(acc[mi][ni][0] + b0, acc[mi][ni][1] + b1);
                *(float2*)(outp + (size_t)(row + 8) * 768 + col0) =
                    make_float2(acc[mi][ni][2] + b0, acc[mi][ni][3] + b1);
            }
        }
    }
}

// =============================================================================
// Kernel 1b: transpose V -> g_vt [B,H,64,N] (validated R9)
// =============================================================================
__global__ __launch_bounds__(256) void v_transpose() {
    __shared__ float sm[64 * 65];
    const int n0 = blockIdx.x * 64;
    const int bh = blockIdx.y;
    const float* src = g_v + ((size_t)bh * 2048 + n0) * 64;
    for (int v = threadIdx.x; v < 1024; v += 256) {
        int i = v >> 4, d4 = (v & 15) << 2;
        float4 t = *(const float4*)(src + i * 64 + d4);
        sm[(d4 + 0) * 65 + i] = t.x; sm[(d4 + 1) * 65 + i] = t.y;
        sm[(d4 + 2) * 65 + i] = t.z; sm[(d4 + 3) * 65 + i] = t.w;
    }
    __syncthreads();
    float* dst = g_vt + (size_t)bh * 64 * 2048 + n0;
    for (int v = threadIdx.x; v < 1024; v += 256) {
        int d = v >> 4, j4 = (v & 15) << 2;
        *(float4*)(dst + (size_t)d * 2048 + j4) =
            make_float4(sm[d * 65 + j4], sm[d * 65 + j4 + 1],
                        sm[d * 65 + j4 + 2], sm[d * 65 + j4 + 3]);
    }
}

// =============================================================================
// Kernel 2: tf32 mma.sync flash attention — 2-stage cp.async pipeline.
// CTA = 128 queries (8 warps x 16 rows) x full key sweep (32 tiles of 64 keys).
// K/Vt double-buffered (prefetch at top of prev iter); dist/mask single-buffered
// (prefetch after softmax reads them, hidden under PV). smem = 113024 B -> 2 CTAs/SM.
// =============================================================================
static constexpr int STG_SZ = 34816;          // per stage: K [64][68] + Vt [64][68]
static constexpr int VT_REL = 17408;          // Vt offset within a stage
static constexpr int DS_OFF = 69632;          // dist [128 q][64] u8 = 8192
static constexpr int MNG_OFF = 77824;         // 64 f32 = 256
static constexpr int PS_OFF = 78080;          // P [128 q][68] f32 = 34816
static constexpr int BT_OFF = 112896;         // 32 f32
static constexpr int ATTN_SMEM = 113024;

__global__ __launch_bounds__(256, 2) void attn_mma(const float* __restrict__ bias_table) {
    extern __shared__ char smem[];
    const uint32_t sb = smem_u32(smem);
    unsigned char* Ds = (unsigned char*)(smem + DS_OFF);
    float* mng = (float*)(smem + MNG_OFF);
    float* Ps = (float*)(smem + PS_OFF);
    float* btc = (float*)(smem + BT_OFF);

    const int tid = threadIdx.x, w = tid >> 5, l = tid & 31;
    const int gid = l >> 2, tig = l & 3;
    const int qt = blockIdx.x, h = blockIdx.y, b = blockIdx.z;
    const size_t bh = (size_t)b * 12 + h;

    const char* kgbase = (const char*)(g_k + (bh * 2048) * 64);
    const char* vgbase = (const char*)(g_vt + bh * 131072);
    const unsigned char* dgbase = g_dist8 + (size_t)(b * 2048 + qt * 128) * 2048;

    // ---- staging helpers (index math validated R9)
    auto stage_kv = [&](int kt, int buf) {
        const uint32_t base = sb + buf * STG_SZ;
#pragma unroll
        for (int j = 0; j < 4; j++) {
            int c = tid + j * 256, r = c >> 4, o = (c & 15) * 16;
            cpa16(base + r * 272 + o, kgbase + ((size_t)(kt * 64 + r) * 256) + o);
        }
#pragma unroll
        for (int j = 0; j < 4; j++) {
            int c = tid + j * 256, r = c >> 4, o = (c & 15) * 16;
            cpa16(base + VT_REL + r * 272 + o, vgbase + ((size_t)r * 8192) + kt * 256 + o);
        }
    };
    auto stage_dm = [&](int kt) {
#pragma unroll
        for (int j = 0; j < 2; j++) {
            int c = tid + j * 256, r = c >> 2, o = (c & 3) * 16;
            cpa16(sb + DS_OFF + r * 64 + o, dgbase + (size_t)r * 2048 + kt * 64 + o);
        }
        if (tid < 16) cpa16(sb + MNG_OFF + tid * 16, g_mneg + b * 2048 + kt * 64 + tid * 4);
    };

    // ---- Q fragments (register-resident)
    uint32_t Qa[8][4];
    {
        const float* qb = g_q + ((bh * 2048) + qt * 128 + w * 16) * 64;
#pragma unroll
        for (int s = 0; s < 8; s++) {
            Qa[s][0] = __float_as_uint(qb[gid * 64 + s * 8 + tig]);
            Qa[s][1] = __float_as_uint(qb[(gid + 8) * 64 + s * 8 + tig]);
            Qa[s][2] = __float_as_uint(qb[gid * 64 + s * 8 + tig + 4]);
            Qa[s][3] = __float_as_uint(qb[(gid + 8) * 64 + s * 8 + tig + 4]);
        }
    }
    if (tid < 32) btc[tid] = bias_table[tid * 12 + h];

    // ---- per-lane LDSM address bases (row pitch 272 B)
    const uint32_t rowB = (l & 7) + ((l >> 4) & 1) * 8;
    const uint32_t colB = ((l >> 3) & 1) * 4;
    const uint32_t kvoff = (rowB * 68 + colB) * 4;   // add stage base + {0, VT_REL}
    const uint32_t prowA = (l & 7) + ((l >> 3) & 1) * 8;
    const uint32_t pcolA = ((l >> 4) & 1) * 4;
    const uint32_t pbase = sb + PS_OFF + ((w * 16 + prowA) * 68 + pcolA) * 4;

    float O[8][4];
#pragma unroll
    for (int n = 0; n < 8; n++)
#pragma unroll
        for (int j = 0; j < 4; j++) O[n][j] = 0.f;
    float lsum0 = 0.f, lsum1 = 0.f;

    // ---- prologue: stage tile 0 (KV + dist + mask) as group 0
    stage_kv(0, 0);
    stage_dm(0);
    CP_COMMIT();

    for (int kt = 0; kt < 32; kt++) {
        // prefetch next KV into the other buffer, then retire this tile's groups.
        // pending at wait: [KV(kt)|g0, D(kt)] (+ KV(kt+1) just committed) -> wait 1/0.
        if (kt < 31) {
            stage_kv(kt + 1, (kt + 1) & 1);
            CP_COMMIT();
            CP_WAIT1();
        } else {
            CP_WAIT0();
        }
        __syncthreads();  // all threads see K/Vt/dist/mng for tile kt

        const uint32_t stg = sb + (kt & 1) * STG_SZ;
        const uint32_t kbase = stg + kvoff;
        const uint32_t vbase = stg + VT_REL + kvoff;

        // ---- S = Q @ K^T : per s-step, 4 LDSM.x4 feed 8 mma
        float S[8][4];
#pragma unroll
        for (int n = 0; n < 8; n++)
#pragma unroll
            for (int j = 0; j < 4; j++) S[n][j] = 0.f;
#pragma unroll
        for (int s = 0; s < 8; s++) {
            uint32_t Bf[4][4];
#pragma unroll
            for (int p = 0; p < 4; p++) ldsm4(Bf[p], kbase + p * 4352 + s * 32);
#pragma unroll
            for (int p = 0; p < 4; p++) {
                mma8(S[2 * p], Qa[s], &Bf[p][0]);
                mma8(S[2 * p + 1], Qa[s], &Bf[p][2]);
            }
        }

        // ---- bias + mask + exp -> Ps
        const unsigned char* d0p = Ds + (w * 16 + gid) * 64;
        const unsigned char* d1p = Ds + (w * 16 + gid + 8) * 64;
        const int prow = w * 16 + gid;
#pragma unroll
        for (int n = 0; n < 8; n++) {
            const int c0 = n * 8 + tig * 2;
            const float mg0 = mng[c0], mg1 = mng[c0 + 1];
            float p00 = to_tf32(__expf(S[n][0] + btc[d0p[c0]] + mg0));
            float p01 = to_tf32(__expf(S[n][1] + btc[d0p[c0 + 1]] + mg1));
            float p10 = to_tf32(__expf(S[n][2] + btc[d1p[c0]] + mg0));
            float p11 = to_tf32(__expf(S[n][3] + btc[d1p[c0 + 1]] + mg1));
            lsum0 += p00 + p01;
            lsum1 += p10 + p11;
            *(float2*)&Ps[prow * 68 + c0] = make_float2(p00, p01);
            *(float2*)&Ps[(prow + 8) * 68 + c0] = make_float2(p10, p11);
        }
        __syncthreads();  // dist/mng(kt) reads done everywhere -> safe to restage

        // prefetch next dist+mask (latency hidden under PV below)
        if (kt < 31) {
            stage_dm(kt + 1);
            CP_COMMIT();
        }

        // ---- O += P @ V : per kk, 1+4 LDSM.x4 feed 8 mma
#pragma unroll
        for (int kk = 0; kk < 8; kk++) {
            uint32_t Pa[4];
            ldsm4(Pa, pbase + kk * 32);
            uint32_t Vf[4][4];
#pragma unroll
            for (int p = 0; p < 4; p++) ldsm4(Vf[p], vbase + p * 4352 + kk * 32);
#pragma unroll
            for (int p = 0; p < 4; p++) {
                mma8(O[2 * p], Pa, &Vf[p][0]);
                mma8(O[2 * p + 1], Pa, &Vf[p][2]);
            }
        }
        __syncthreads();  // KV buf(kt&1) reads done -> next-top restage is safe
    }

    // ---- epilogue: quad-reduce row sums, normalize, write g_ao
    lsum0 += __shfl_xor_sync(0xffffffffu, lsum0, 1);
    lsum0 += __shfl_xor_sync(0xffffffffu, lsum0, 2);
    lsum1 += __shfl_xor_sync(0xffffffffu, lsum1, 1);
    lsum1 += __shfl_xor_sync(0xffffffffu, lsum1, 2);
    const float inv0 = 1.0f / lsum0, inv1 = 1.0f / lsum1;
    float* dst = g_ao + ((size_t)b * 2048 + qt * 128 + w * 16) * 768 + h * 64;
#pragma unroll
    for (int n = 0; n < 8; n++) {
        const int c0 = n * 8 + tig * 2;
        *(float2*)&dst[gid * 768 + c0] = make_float2(O[n][0] * inv0, O[n][1] * inv0);
        *(float2*)&dst[(gid + 8) * 768 + c0] = make_float2(O[n][2] * inv1, O[n][3] * inv1);
    }
}

// =============================================================================
extern "C" void kernel_launch(void* const* d_in, const int* in_sizes, int n_in,
                              void* d_out, int out_size) {
    const float* x         = (const float*)d_in[0];
    const int* dist        = (const int*)d_in[1];
    const unsigned int* mk = (const unsigned int*)d_in[2];
    const float* qkv_w     = (const float*)d_in[3];
    const float* qkv_b     = (const float*)d_in[4];
    const float* out_w     = (const float*)d_in[5];
    const float* out_b     = (const float*)d_in[6];
    const float* bt        = (const float*)d_in[7];
    float* out             = (float*)d_out;

    mask_prep<<<1, 256>>>(mk);
    dist_pack<<<4096, 256>>>(dist);

    dim3 g1(18, 32);
    gemm_tc<<<g1, 256>>>(x, qkv_w, qkv_b, nullptr, 2304, 0);

    dim3 gt(32, 24);
    v_transpose<<<gt, 256>>>();

    cudaFuncSetAttribute(attn_mma, cudaFuncAttributeMaxDynamicSharedMemorySize, ATTN_SMEM);
    dim3 g2(16, 12, 2);
    attn_mma<<<g2, 256, ATTN_SMEM>>>(bt);

    dim3 g3(6, 32);
    gemm_tc<<<g3, 256>>>(nullptr, out_w, out_b, out, 768, 1);
}

// round 11
// speedup vs baseline: 3.8562x; 1.1336x over previous
#include <cuda_runtime.h>
#include <cstdint>

// ---------------- scratch (allocation-free rule: __device__ globals) ----------
// g_q/g_k/g_v : [B,H,N,64] (tf32-rounded; q pre-scaled by 0.125)
// g_vt : [B,H,64,N] (V transposed)   g_ao : [B,N,768]
__device__ float g_q[2 * 12 * 2048 * 64];
__device__ float g_k[2 * 12 * 2048 * 64];
__device__ float g_v[2 * 12 * 2048 * 64];
__device__ float g_vt[2 * 12 * 64 * 2048];
__device__ float g_ao[2 * 2048 * 768];
__device__ float g_mneg[2 * 2048];                  // 0 or -1e30 per key
__device__ unsigned char g_dist8[2 * 2048 * 2048];  // clipped dist, 1 byte

__device__ __forceinline__ float to_tf32(float x) {
    float r;
    asm("cvt.rna.tf32.f32 %0, %1;" : "=f"(r) : "f"(x));
    return r;
}
__device__ __forceinline__ void mma8(float* c, const uint32_t* a, const uint32_t* b) {
    asm("mma.sync.aligned.m16n8k8.row.col.f32.tf32.tf32.f32 "
        "{%0,%1,%2,%3},{%4,%5,%6,%7},{%8,%9},{%0,%1,%2,%3};"
        : "+f"(c[0]), "+f"(c[1]), "+f"(c[2]), "+f"(c[3])
        : "r"(a[0]), "r"(a[1]), "r"(a[2]), "r"(a[3]), "r"(b[0]), "r"(b[1]));
}
__device__ __forceinline__ uint32_t smem_u32(const void* p) {
    uint32_t a;
    asm("{ .reg .u64 t; cvta.to.shared.u64 t, %1; cvt.u32.u64 %0, t; }" : "=r"(a) : "l"(p));
    return a;
}
// tf32 fragments via b16 ldmatrix: lane l <- (row l/4, col l%4) per 8x4-tf32 tile
__device__ __forceinline__ void ldsm4(uint32_t* r, uint32_t addr) {
    asm volatile("ldmatrix.sync.aligned.m8n8.x4.shared.b16 {%0,%1,%2,%3}, [%4];"
                 : "=r"(r[0]), "=r"(r[1]), "=r"(r[2]), "=r"(r[3]) : "r"(addr));
}
__device__ __forceinline__ void cpa16(uint32_t saddr, const void* g) {
    asm volatile("cp.async.cg.shared.global [%0], [%1], 16;" :: "r"(saddr), "l"(g));
}
#define CP_COMMIT() asm volatile("cp.async.commit_group;" ::: "memory")
#define CP_WAIT0()  asm volatile("cp.async.wait_group 0;" ::: "memory")

// =============================================================================
// Kernel 0a: mask dtype sniffer + conversion (validated R3)
// =============================================================================
__global__ void mask_prep(const unsigned int* __restrict__ mw) {
    const int tid = threadIdx.x;
    int ok_int = 1, ok_flt = 1;
    for (int i = tid; i < 1024; i += 256) {
        unsigned int v = mw[i];
        if (v != 0u && v != 1u) ok_int = 0;
        if (v != 0u && v != 0x3F800000u) ok_flt = 0;
    }
    ok_int = __syncthreads_and(ok_int);
    ok_flt = __syncthreads_and(ok_flt);
    if (ok_int) {
        const int* m = (const int*)mw;
        for (int i = tid; i < 4096; i += 256) g_mneg[i] = m[i] ? -1e30f : 0.0f;
    } else if (ok_flt) {
        const float* m = (const float*)mw;
        for (int i = tid; i < 4096; i += 256) g_mneg[i] = (m[i] != 0.0f) ? -1e30f : 0.0f;
    } else {
        const unsigned char* m = (const unsigned char*)mw;
        for (int i = tid; i < 4096; i += 256) g_mneg[i] = m[i] ? -1e30f : 0.0f;
    }
}

// =============================================================================
// Kernel 0b: pack dist int32 -> clipped uint8 (validated R6)
// =============================================================================
__global__ void dist_pack(const int* __restrict__ dist) {
    size_t i = ((size_t)blockIdx.x * 256 + threadIdx.x) * 8;
    int4 a = *(const int4*)(dist + i);
    int4 b = *(const int4*)(dist + i + 4);
    unsigned c0 = (unsigned)min(max(a.x, 0), 31) | ((unsigned)min(max(a.y, 0), 31) << 8) |
                  ((unsigned)min(max(a.z, 0), 31) << 16) | ((unsigned)min(max(a.w, 0), 31) << 24);
    unsigned c1 = (unsigned)min(max(b.x, 0), 31) | ((unsigned)min(max(b.y, 0), 31) << 8) |
                  ((unsigned)min(max(b.z, 0), 31) << 16) | ((unsigned)min(max(b.w, 0), 31) << 24);
    *(uint2*)(g_dist8 + i) = make_uint2(c0, c1);
}

// =============================================================================
// Kernel 1: tf32 tensor-core GEMM v2 — cp.async double-buffered + LDSM A-frags.
// C[4096, N] = tf32(A[4096,768]) @ tf32(W[768,N]) + b ; 128x128 tile, BK=16.
// Inputs HW-truncated to tf32 by mma (cp.async path has no rna round).
// One __syncthreads per k-step: stage(ks+1) issued AFTER the barrier, so the
// buffer it overwrites (used in ks-1) is guaranteed drained.
// =============================================================================
__global__ __launch_bounds__(256) void gemm_tc(const float* __restrict__ A,
                                               const float* __restrict__ W,
                                               const float* __restrict__ Bv,
                                               float* __restrict__ outp,
                                               int N, int mode) {
    if (mode == 1) A = g_ao;  // device-side symbol reference (R7 fix)
    __shared__ float As[2][128][20];   // [m][k], 80B pitch (16B-aligned, LDSM-ok)
    __shared__ float Bs[2][16][136];
    const int tid = threadIdx.x, w = tid >> 5, l = tid & 31;
    const int gid = l >> 2, tig = l & 3;
    const int wm = w >> 2, wn = w & 3;
    const int bM = blockIdx.y * 128, bN = blockIdx.x * 128;
    const uint32_t sb_a = smem_u32(&As[0][0][0]);
    const uint32_t sb_b = smem_u32(&Bs[0][0][0]);

    auto stage = [&](int k0, int buf) {
#pragma unroll
        for (int j = 0; j < 2; j++) {  // A: 128 rows x 64B
            int c = tid + j * 256, r = c >> 2, o = c & 3;
            cpa16(sb_a + buf * 10240 + r * 80 + o * 16,
                  A + (size_t)(bM + r) * 768 + k0 + o * 4);
        }
#pragma unroll
        for (int j = 0; j < 2; j++) {  // B: 16 rows x 512B
            int c = tid + j * 256, r = c >> 5, o = c & 31;
            cpa16(sb_b + buf * 8704 + r * 544 + o * 16,
                  W + (size_t)(k0 + r) * N + bN + o * 4);
        }
    };

    float acc[4][4][4];
#pragma unroll
    for (int mi = 0; mi < 4; mi++)
#pragma unroll
        for (int ni = 0; ni < 4; ni++)
#pragma unroll
            for (int j = 0; j < 4; j++) acc[mi][ni][j] = 0.f;

    // LDSM A-fragment lane addressing (same map as attention P, validated R9)
    const uint32_t prowA = (l & 7) + ((l >> 3) & 1) * 8;
    const uint32_t pcolA = ((l >> 4) & 1) * 4;

    stage(0, 0);
    CP_COMMIT();

    for (int ks = 0; ks < 48; ks++) {
        CP_WAIT0();
        __syncthreads();  // all threads' copies for tile ks visible; ks-1 drained
        if (ks < 47) { stage((ks + 1) * 16, (ks + 1) & 1); CP_COMMIT(); }
        const int buf = ks & 1;
        const uint32_t abase = sb_a + buf * 10240;

#pragma unroll
        for (int kk = 0; kk < 2; kk++) {
            const int kb = kk * 8;
            uint32_t Af[4][4], Bf[4][2];
#pragma unroll
            for (int mi = 0; mi < 4; mi++) {
                const int m0 = wm * 64 + mi * 16;
                ldsm4(Af[mi], abase + (m0 + prowA) * 80 + (kb + pcolA) * 4);
            }
#pragma unroll
            for (int ni = 0; ni < 4; ni++) {
                const int n0 = wn * 32 + ni * 8 + gid;
                Bf[ni][0] = __float_as_uint(Bs[buf][kb + tig][n0]);
                Bf[ni][1] = __float_as_uint(Bs[buf][kb + tig + 4][n0]);
            }
#pragma unroll
            for (int mi = 0; mi < 4; mi++)
#pragma unroll
                for (int ni = 0; ni < 4; ni++) mma8(acc[mi][ni], Af[mi], Bf[ni]);
        }
    }

    // ---- epilogue (validated R8)
#pragma unroll
    for (int ni = 0; ni < 4; ni++) {
        const int col0 = bN + wn * 32 + ni * 8 + tig * 2;
        const float b0 = Bv[col0], b1 = Bv[col0 + 1];
        if (mode == 0) {
            const int which = col0 / 768;
            const int rem = col0 % 768;
            const int hh = rem / 64, hd0 = rem % 64;
            float* dst = (which == 0) ? g_q : (which == 1 ? g_k : g_v);
            const float qs = (which == 0) ? 0.125f : 1.0f;
#pragma unroll
            for (int mi = 0; mi < 4; mi++) {
                const int row = bM + wm * 64 + mi * 16 + gid;
                const int bidx = row >> 11, n = row & 2047;
                float* p = dst + ((((size_t)bidx * 12 + hh) * 2048 + n) * 64 + hd0);
                *(float2*)p = make_float2(to_tf32((acc[mi][ni][0] + b0) * qs),
                                          to_tf32((acc[mi][ni][1] + b1) * qs));
                const int row2 = row + 8;
                const int bidx2 = row2 >> 11, n2 = row2 & 2047;
                float* p2 = dst + ((((size_t)bidx2 * 12 + hh) * 2048 + n2) * 64 + hd0);
                *(float2*)p2 = make_float2(to_tf32((acc[mi][ni][2] + b0) * qs),
                                           to_tf32((acc[mi][ni][3] + b1) * qs));
            }
        } else {
#pragma unroll
            for (int mi = 0; mi < 4; mi++) {
                const int row = bM + wm * 64 + mi * 16 + gid;
                *(float2*)(outp + (size_t)row * 768 + col0) =
                    make_float2(acc[mi][ni][0] + b0, acc[mi][ni][1] + b1);
                *(float2*)(outp + (size_t)(row + 8) * 768 + col0) =
                    make_float2(acc[mi][ni][2] + b0, acc[mi][ni][3] + b1);
            }
        }
    }
}

// =============================================================================
// Kernel 1b: transpose V -> g_vt [B,H,64,N] (validated R9)
// =============================================================================
__global__ __launch_bounds__(256) void v_transpose() {
    __shared__ float sm[64 * 65];
    const int n0 = blockIdx.x * 64;
    const int bh = blockIdx.y;
    const float* src = g_v + ((size_t)bh * 2048 + n0) * 64;
    for (int v = threadIdx.x; v < 1024; v += 256) {
        int i = v >> 4, d4 = (v & 15) << 2;
        float4 t = *(const float4*)(src + i * 64 + d4);
        sm[(d4 + 0) * 65 + i] = t.x; sm[(d4 + 1) * 65 + i] = t.y;
        sm[(d4 + 2) * 65 + i] = t.z; sm[(d4 + 3) * 65 + i] = t.w;
    }
    __syncthreads();
    float* dst = g_vt + (size_t)bh * 64 * 2048 + n0;
    for (int v = threadIdx.x; v < 1024; v += 256) {
        int d = v >> 4, j4 = (v & 15) << 2;
        *(float4*)(dst + (size_t)d * 2048 + j4) =
            make_float4(sm[d * 65 + j4], sm[d * 65 + j4 + 1],
                        sm[d * 65 + j4 + 2], sm[d * 65 + j4 + 3]);
    }
}

// =============================================================================
// Kernel 2: tf32 mma.sync flash attention — barrier-diet edition.
// 1 __syncthreads + 1 __syncwarp per key tile (was 3 barriers):
//  - mask moved into the double-buffered KV stage (hazard = buffering)
//  - dist staged warp-locally (warp w owns its 16 query rows) -> syncwarp reuse
//  - end-of-tile barrier dropped: all restages issue after the top barrier
// =============================================================================
static constexpr int VT_REL = 17408;          // Vt offset within a stage
static constexpr int MNG_REL = 34816;         // mask offset within a stage
static constexpr int STG_SZ = 35072;          // K[64][68] + Vt[64][68] + mng[64]
static constexpr int DS_OFF = 70144;          // dist [128 q][64] u8 = 8192
static constexpr int PS_OFF = 78336;          // P [128 q][68] f32 = 34816
static constexpr int BT_OFF = 113152;         // 32 f32
static constexpr int ATTN_SMEM = 113280;      // <= 114688 -> 2 CTAs/SM

__global__ __launch_bounds__(256, 2) void attn_mma(const float* __restrict__ bias_table) {
    extern __shared__ char smem[];
    const uint32_t sb = smem_u32(smem);
    unsigned char* Ds = (unsigned char*)(smem + DS_OFF);
    float* Ps = (float*)(smem + PS_OFF);
    float* btc = (float*)(smem + BT_OFF);

    const int tid = threadIdx.x, w = tid >> 5, l = tid & 31;
    const int gid = l >> 2, tig = l & 3;
    const int qt = blockIdx.x, h = blockIdx.y, b = blockIdx.z;
    const size_t bh = (size_t)b * 12 + h;

    const char* kgbase = (const char*)(g_k + (bh * 2048) * 64);
    const char* vgbase = (const char*)(g_vt + bh * 131072);
    const unsigned char* dgbase = g_dist8 + (size_t)(b * 2048 + qt * 128) * 2048;

    auto stage_kv = [&](int kt, int buf) {
        const uint32_t base = sb + buf * STG_SZ;
#pragma unroll
        for (int j = 0; j < 4; j++) {
            int c = tid + j * 256, r = c >> 4, o = (c & 15) * 16;
            cpa16(base + r * 272 + o, kgbase + ((size_t)(kt * 64 + r) * 256) + o);
        }
#pragma unroll
        for (int j = 0; j < 4; j++) {
            int c = tid + j * 256, r = c >> 4, o = (c & 15) * 16;
            cpa16(base + VT_REL + r * 272 + o, vgbase + ((size_t)r * 8192) + kt * 256 + o);
        }
        if (tid < 16) cpa16(base + MNG_REL + tid * 16, g_mneg + b * 2048 + kt * 64 + tid * 4);
    };
    // warp-local: warp w stages dist rows w*16 .. w*16+15 (its own query rows)
    auto stage_dm = [&](int kt) {
#pragma unroll
        for (int j = 0; j < 2; j++) {
            int c = l + j * 32, r = w * 16 + (c >> 2), o = (c & 3) * 16;
            cpa16(sb + DS_OFF + r * 64 + o, dgbase + (size_t)r * 2048 + kt * 64 + o);
        }
    };

    // ---- Q fragments (register-resident)
    uint32_t Qa[8][4];
    {
        const float* qb = g_q + ((bh * 2048) + qt * 128 + w * 16) * 64;
#pragma unroll
        for (int s = 0; s < 8; s++) {
            Qa[s][0] = __float_as_uint(qb[gid * 64 + s * 8 + tig]);
            Qa[s][1] = __float_as_uint(qb[(gid + 8) * 64 + s * 8 + tig]);
            Qa[s][2] = __float_as_uint(qb[gid * 64 + s * 8 + tig + 4]);
            Qa[s][3] = __float_as_uint(qb[(gid + 8) * 64 + s * 8 + tig + 4]);
        }
    }
    if (tid < 32) btc[tid] = bias_table[tid * 12 + h];

    // ---- per-lane LDSM address bases (row pitch 272 B)
    const uint32_t rowB = (l & 7) + ((l >> 4) & 1) * 8;
    const uint32_t colB = ((l >> 3) & 1) * 4;
    const uint32_t kvoff = (rowB * 68 + colB) * 4;
    const uint32_t prowA = (l & 7) + ((l >> 3) & 1) * 8;
    const uint32_t pcolA = ((l >> 4) & 1) * 4;
    const uint32_t pbase = sb + PS_OFF + ((w * 16 + prowA) * 68 + pcolA) * 4;

    float O[8][4];
#pragma unroll
    for (int n = 0; n < 8; n++)
#pragma unroll
        for (int j = 0; j < 4; j++) O[n][j] = 0.f;
    float lsum0 = 0.f, lsum1 = 0.f;

    // ---- prologue: stage tile 0 fully
    stage_kv(0, 0);
    stage_dm(0);
    CP_COMMIT();

    for (int kt = 0; kt < 32; kt++) {
        CP_WAIT0();       // retires KV(kt)+mng(kt)+dist(kt)
        __syncthreads();  // block-wide visibility; prior tile fully drained
        if (kt < 31) { stage_kv(kt + 1, (kt + 1) & 1); CP_COMMIT(); }

        const uint32_t stg = sb + (kt & 1) * STG_SZ;
        const uint32_t kbase = stg + kvoff;
        const uint32_t vbase = stg + VT_REL + kvoff;
        const float* mng = (const float*)(smem + (kt & 1) * STG_SZ + MNG_REL);

        // ---- S = Q @ K^T
        float S[8][4];
#pragma unroll
        for (int n = 0; n < 8; n++)
#pragma unroll
            for (int j = 0; j < 4; j++) S[n][j] = 0.f;
#pragma unroll
        for (int s = 0; s < 8; s++) {
            uint32_t Bf[4][4];
#pragma unroll
            for (int p = 0; p < 4; p++) ldsm4(Bf[p], kbase + p * 4352 + s * 32);
#pragma unroll
            for (int p = 0; p < 4; p++) {
                mma8(S[2 * p], Qa[s], &Bf[p][0]);
                mma8(S[2 * p + 1], Qa[s], &Bf[p][2]);
            }
        }

        // ---- bias + mask + exp -> Ps
        const unsigned char* d0p = Ds + (w * 16 + gid) * 64;
        const unsigned char* d1p = Ds + (w * 16 + gid + 8) * 64;
        const int prow = w * 16 + gid;
#pragma unroll
        for (int n = 0; n < 8; n++) {
            const int c0 = n * 8 + tig * 2;
            const float mg0 = mng[c0], mg1 = mng[c0 + 1];
            float p00 = to_tf32(__expf(S[n][0] + btc[d0p[c0]] + mg0));
            float p01 = to_tf32(__expf(S[n][1] + btc[d0p[c0 + 1]] + mg1));
            float p10 = to_tf32(__expf(S[n][2] + btc[d1p[c0]] + mg0));
            float p11 = to_tf32(__expf(S[n][3] + btc[d1p[c0 + 1]] + mg1));
            lsum0 += p00 + p01;
            lsum1 += p10 + p11;
            *(float2*)&Ps[prow * 68 + c0] = make_float2(p00, p01);
            *(float2*)&Ps[(prow + 8) * 68 + c0] = make_float2(p10, p11);
        }
        __syncwarp();  // warp done reading its own dist rows -> safe to restage
        if (kt < 31) { stage_dm(kt + 1); CP_COMMIT(); }

        // ---- O += P @ V
#pragma unroll
        for (int kk = 0; kk < 8; kk++) {
            uint32_t Pa[4];
            ldsm4(Pa, pbase + kk * 32);
            uint32_t Vf[4][4];
#pragma unroll
            for (int p = 0; p < 4; p++) ldsm4(Vf[p], vbase + p * 4352 + kk * 32);
#pragma unroll
            for (int p = 0; p < 4; p++) {
                mma8(O[2 * p], Pa, &Vf[p][0]);
                mma8(O[2 * p + 1], Pa, &Vf[p][2]);
            }
        }
        // no end barrier: next tile's restages all sit after the next top barrier
    }

    // ---- epilogue: quad-reduce row sums, normalize, write g_ao
    lsum0 += __shfl_xor_sync(0xffffffffu, lsum0, 1);
    lsum0 += __shfl_xor_sync(0xffffffffu, lsum0, 2);
    lsum1 += __shfl_xor_sync(0xffffffffu, lsum1, 1);
    lsum1 += __shfl_xor_sync(0xffffffffu, lsum1, 2);
    const float inv0 = 1.0f / lsum0, inv1 = 1.0f / lsum1;
    float* dst = g_ao + ((size_t)b * 2048 + qt * 128 + w * 16) * 768 + h * 64;
#pragma unroll
    for (int n = 0; n < 8; n++) {
        const int c0 = n * 8 + tig * 2;
        *(float2*)&dst[gid * 768 + c0] = make_float2(O[n][0] * inv0, O[n][1] * inv0);
        *(float2*)&dst[(gid + 8) * 768 + c0] = make_float2(O[n][2] * inv1, O[n][3] * inv1);
    }
}

// =============================================================================
extern "C" void kernel_launch(void* const* d_in, const int* in_sizes, int n_in,
                              void* d_out, int out_size) {
    const float* x         = (const float*)d_in[0];
    const int* dist        = (const int*)d_in[1];
    const unsigned int* mk = (const unsigned int*)d_in[2];
    const float* qkv_w     = (const float*)d_in[3];
    const float* qkv_b     = (const float*)d_in[4];
    const float* out_w     = (const float*)d_in[5];
    const float* out_b     = (const float*)d_in[6];
    const float* bt        = (const float*)d_in[7];
    float* out             = (float*)d_out;

    mask_prep<<<1, 256>>>(mk);
    dist_pack<<<4096, 256>>>(dist);

    dim3 g1(18, 32);
    gemm_tc<<<g1, 256>>>(x, qkv_w, qkv_b, nullptr, 2304, 0);

    dim3 gt(32, 24);
    v_transpose<<<gt, 256>>>();

    cudaFuncSetAttribute(attn_mma, cudaFuncAttributeMaxDynamicSharedMemorySize, ATTN_SMEM);
    dim3 g2(16, 12, 2);
    attn_mma<<<g2, 256, ATTN_SMEM>>>(bt);

    dim3 g3(6, 32);
    gemm_tc<<<g3, 256>>>(nullptr, out_w, out_b, out, 768, 1);
}